// round 7
// baseline (speedup 1.0000x reference)
#include <cuda_runtime.h>
#include <cuda_fp16.h>
#include <cstdint>

// ---------------- problem constants ----------------
#define BATCH   2048
#define RDIM    256
#define HIDD    256
#define CONDD   128
#define ZCD     384
#define NCHD    64
#define MAXLEN  128
#define CLUSTER 8
#define MROWS   128            // batch rows per cluster (and per-CTA M)
#define NBLK    128            // 16 clusters * 8 CTAs
#define NT      256            // 8 warps
#define NTILES  17             // n8 tiles per CTA: 16 gate + 1 logits
#define KTILES  16
#define APITCH  264            // fp16 pitch of A plane (conflict-free)

#define W_U4    (KTILES*NTILES*32)   // 8704 uint4 per CTA slice
#define W_BYTES (W_U4*16)            // 139264
#define A_BYTES (MROWS*APITCH*2)     // 67584
#define H_BYTES (MROWS*32*4)         // 16384
#define OFF_W   0
#define OFF_A   W_BYTES
#define OFF_H   (OFF_A + A_BYTES)
#define OFF_B   (OFF_H + H_BYTES)
#define SMEM_DYN (OFF_B + 1024)      // 224256 bytes

// ---------------- device-global scratch ----------------
__device__ __align__(16) uint4 g_wfrag[8 * W_U4];   // per-slice fragment-packed W (fp16 hi/lo)
__device__ float g_h1[BATCH * RDIM];                 // h after step 0 (exact fp32)
__device__ float g_WhhT[RDIM * 768];                 // Whh transposed [k][row]
__device__ float g_WlhT[ZCD * RDIM];                 // Wlh transposed [k][col]

// ---------------- helpers ----------------
__device__ __forceinline__ float sigf(float x) { return 1.0f / (1.0f + __expf(-x)); }
__device__ __forceinline__ float tanha(float x) {
    float y; asm("tanh.approx.f32 %0, %1;" : "=f"(y) : "f"(x)); return y;
}
__device__ __forceinline__ uint16_t h_hi(float x) {
    __half h = __float2half_rn(x); return __half_as_ushort(h);
}
__device__ __forceinline__ uint16_t h_lo(float x) {
    __half h = __float2half_rn(x);
    return __half_as_ushort(__float2half_rn(x - __half2float(h)));
}
__device__ __forceinline__ uint32_t smem_u32(const void* p) {
    uint32_t a;
    asm("{ .reg .u64 t; cvta.to.shared.u64 t, %1; cvt.u32.u64 %0, t; }" : "=r"(a) : "l"(p));
    return a;
}
#define CLUSTER_SYNC() do { \
    asm volatile("barrier.cluster.arrive.aligned;" ::: "memory"); \
    asm volatile("barrier.cluster.wait.aligned;"   ::: "memory"); \
} while (0)

// m16n8k16 row.col fp16 -> f32 accumulate (generic PTX)
__device__ __forceinline__ void mma16816(float* d, uint32_t a0, uint32_t a1, uint32_t a2, uint32_t a3,
                                         uint32_t b0, uint32_t b1) {
    asm volatile(
        "mma.sync.aligned.m16n8k16.row.col.f32.f16.f16.f32 "
        "{%0,%1,%2,%3}, {%4,%5,%6,%7}, {%8,%9}, {%0,%1,%2,%3};"
        : "+f"(d[0]), "+f"(d[1]), "+f"(d[2]), "+f"(d[3])
        : "r"(a0), "r"(a1), "r"(a2), "r"(a3), "r"(b0), "r"(b1));
}

// ---------------- prep: pack W fragments + transposes ----------------
__device__ __forceinline__ float wval_g(const float* Wih, const float* Whh, const float* Wout,
                                        int s, int nt, int q, int k) {
    if (nt < 16) {
        int nl = nt * 8 + q;
        int hc = s * 32 + (nl >> 2);
        int g  = nl & 3;
        if (g == 0) return Wih[hc*RDIM+k] + Whh[hc*RDIM+k];
        if (g == 1) return Wih[(256+hc)*RDIM+k] + Whh[(256+hc)*RDIM+k];
        if (g == 2) return Wih[(512+hc)*RDIM+k];
        return Whh[(512+hc)*RDIM+k];
    }
    return Wout[(s*8 + q)*RDIM + k];
}

__global__ void prep_kernel(const float* __restrict__ Wih,
                            const float* __restrict__ Whh,
                            const float* __restrict__ Wout,
                            const float* __restrict__ Wlh) {
    int i0 = blockIdx.x * blockDim.x + threadIdx.x;
    int stride = gridDim.x * blockDim.x;

    const int TOT = 8 * W_U4;   // 69632
    for (int idx = i0; idx < TOT; idx += stride) {
        int lane = idx & 31;
        int nt   = (idx >> 5) % NTILES;
        int kt   = (idx / (32 * NTILES)) % KTILES;
        int s    = idx / (32 * NTILES * KTILES);
        int q    = lane >> 2;
        int c    = lane & 3;
        int k0   = kt * 16 + 2 * c;
        float w00 = wval_g(Wih, Whh, Wout, s, nt, q, k0);
        float w01 = wval_g(Wih, Whh, Wout, s, nt, q, k0 + 1);
        float w10 = wval_g(Wih, Whh, Wout, s, nt, q, k0 + 8);
        float w11 = wval_g(Wih, Whh, Wout, s, nt, q, k0 + 9);
        uint4 o;
        o.x = (uint32_t)h_hi(w00) | ((uint32_t)h_hi(w01) << 16);
        o.y = (uint32_t)h_hi(w10) | ((uint32_t)h_hi(w11) << 16);
        o.z = (uint32_t)h_lo(w00) | ((uint32_t)h_lo(w01) << 16);
        o.w = (uint32_t)h_lo(w10) | ((uint32_t)h_lo(w11) << 16);
        g_wfrag[idx] = o;
    }
    for (int idx = i0; idx < RDIM * 768; idx += stride) {
        int k = idx / 768, row = idx % 768;
        g_WhhT[idx] = Whh[row * RDIM + k];
    }
    for (int idx = i0; idx < ZCD * RDIM; idx += stride) {
        int k = idx >> 8, c = idx & 255;
        g_WlhT[idx] = Wlh[c * ZCD + k];
    }
}

// ---------------- pre-kernel: h0 = Wlh [z,xc] + b ; h1 = GRU(0, h0) exact fp32 ----------------
__global__ void __launch_bounds__(256)
pre_kernel(const float* __restrict__ z, const float* __restrict__ xc,
           const float* __restrict__ blh, const float* __restrict__ bih,
           const float* __restrict__ bhh) {
    __shared__ __align__(16) float zc_s[16 * ZCD];
    __shared__ __align__(16) float h0_s[16 * RDIM];
    const int tid  = threadIdx.x;
    const int row0 = blockIdx.x * 16;

    for (int i = tid; i < 16 * HIDD; i += 256) {
        int r = i / HIDD, c = i % HIDD;
        zc_s[r * ZCD + c] = z[(row0 + r) * HIDD + c];
    }
    for (int i = tid; i < 16 * CONDD; i += 256) {
        int r = i / CONDD, c = i % CONDD;
        zc_s[r * ZCD + HIDD + c] = xc[(row0 + r) * CONDD + c];
    }
    __syncthreads();

    // h0
    {
        float acc[16];
        float bv = blh[tid];
        #pragma unroll
        for (int r = 0; r < 16; ++r) acc[r] = bv;
        for (int k = 0; k < ZCD; ++k) {
            float w = g_WlhT[k * RDIM + tid];
            #pragma unroll
            for (int r = 0; r < 16; ++r)
                acc[r] = fmaf(zc_s[r * ZCD + k], w, acc[r]);
        }
        #pragma unroll
        for (int r = 0; r < 16; ++r) h0_s[r * RDIM + tid] = acc[r];
    }
    __syncthreads();

    // step 0 with x = 0: gi = b_ih, gh = Whh h0 + b_hh
    float aR[16], aU[16], aH[16];
    #pragma unroll
    for (int r = 0; r < 16; ++r) { aR[r] = 0.f; aU[r] = 0.f; aH[r] = 0.f; }
    for (int k = 0; k < RDIM; ++k) {
        float wr = g_WhhT[k * 768 + tid];
        float wu = g_WhhT[k * 768 + 256 + tid];
        float wn = g_WhhT[k * 768 + 512 + tid];
        #pragma unroll
        for (int r = 0; r < 16; ++r) {
            float hv = h0_s[r * RDIM + k];
            aR[r] = fmaf(hv, wr, aR[r]);
            aU[r] = fmaf(hv, wu, aU[r]);
            aH[r] = fmaf(hv, wn, aH[r]);
        }
    }
    const float br = bih[tid] + bhh[tid];
    const float bu = bih[256 + tid] + bhh[256 + tid];
    const float bi = bih[512 + tid];
    const float bh = bhh[512 + tid];
    #pragma unroll
    for (int r = 0; r < 16; ++r) {
        float rg = sigf(aR[r] + br);
        float ug = sigf(aU[r] + bu);
        float nn = tanhf(fmaf(rg, aH[r] + bh, bi));
        float h1 = fmaf(ug, h0_s[r * RDIM + tid] - nn, nn);
        g_h1[(row0 + r) * RDIM + tid] = h1;
    }
}

// ---------------- main persistent cluster kernel ----------------
__global__ void __launch_bounds__(NT, 1) __cluster_dims__(CLUSTER, 1, 1)
gru_main_kernel(const float* __restrict__ bih, const float* __restrict__ bhh,
                const float* __restrict__ bout, float* __restrict__ out) {
    extern __shared__ __align__(16) char smem[];
    uint4*  w_s  = reinterpret_cast<uint4*>(smem + OFF_W);
    __half* a_s  = reinterpret_cast<__half*>(smem + OFF_A);
    float*  h_s  = reinterpret_cast<float*>(smem + OFF_H);
    float*  bias = reinterpret_cast<float*>(smem + OFF_B);

    const int tid  = threadIdx.x;
    const int wid  = tid >> 5;
    const int lane = tid & 31;
    const int cc   = lane & 3;
    const int gID  = lane >> 2;
    uint32_t rank;
    asm("mov.u32 %0, %%cluster_ctarank;" : "=r"(rank));
    const int s    = (int)rank;
    const int m    = blockIdx.x / CLUSTER;
    const int row0 = m * MROWS;
    const int wrow = (wid << 4) + gID;   // tile-local row for this thread's m16 tile

    // ---- resident weight fragments ----
    const uint4* wg = g_wfrag + (size_t)s * W_U4;
    for (int i = tid; i < W_U4; i += NT) w_s[i] = wg[i];

    // ---- A plane (fp16) + own fp32 slice from h1 ----
    for (int i = tid; i < MROWS * RDIM; i += NT) {
        int r = i >> 8, k = i & 255;
        a_s[r * APITCH + k] = __float2half_rn(g_h1[(row0 + r) * RDIM + k]);
    }
    for (int i = tid; i < MROWS * 32; i += NT) {
        int r = i >> 5, c = i & 31;
        h_s[i] = g_h1[(row0 + r) * RDIM + s * 32 + c];
    }
    if (tid < 32) {
        int hcol = s * 32 + tid;
        bias[tid]      = bih[hcol] + bhh[hcol];
        bias[32 + tid] = bih[256 + hcol] + bhh[256 + hcol];
        bias[64 + tid] = bih[512 + hcol];
        bias[96 + tid] = bhh[512 + hcol];
    }
    if (tid < 8) bias[128 + tid] = bout[s * 8 + tid];
    CLUSTER_SYNC();

    // mapa bases for the 8 cluster A-planes
    uint32_t a_base = smem_u32(a_s);
    uint32_t pa[8];
    #pragma unroll
    for (int r = 0; r < 8; ++r)
        asm("mapa.shared::cluster.u32 %0, %1, %2;" : "=r"(pa[r]) : "r"(a_base), "r"(r));

    #pragma unroll 1
    for (int j = 1; j <= MAXLEN; ++j) {
        float d[NTILES][4];
        #pragma unroll
        for (int n = 0; n < NTILES; ++n) { d[n][0]=0.f; d[n][1]=0.f; d[n][2]=0.f; d[n][3]=0.f; }

        // ---- K loop: pure LDS + MMA, zero syncs ----
        #pragma unroll 1
        for (int kt = 0; kt < KTILES; ++kt) {
            const int k0 = kt * 16 + 2 * cc;
            uint32_t a0 = *reinterpret_cast<const uint32_t*>(a_s + wrow * APITCH + k0);
            uint32_t a1 = *reinterpret_cast<const uint32_t*>(a_s + (wrow + 8) * APITCH + k0);
            uint32_t a2 = *reinterpret_cast<const uint32_t*>(a_s + wrow * APITCH + k0 + 8);
            uint32_t a3 = *reinterpret_cast<const uint32_t*>(a_s + (wrow + 8) * APITCH + k0 + 8);
            #pragma unroll
            for (int n = 0; n < NTILES; ++n) {
                uint4 B = w_s[(kt * NTILES + n) * 32 + lane];
                mma16816(d[n], a0, a1, a2, a3, B.x, B.y);   // Whi * A
                mma16816(d[n], a0, a1, a2, a3, B.z, B.w);   // Wlo * A
            }
        }

        CLUSTER_SYNC();   // everyone finished reading A planes

        // ---- logits for output index j-1 (ntile 16) ----
        {
            const int oc = 2 * cc;
            const size_t o0 = ((size_t)(row0 + wrow) * MAXLEN + (j - 1)) * NCHD + s * 8 + oc;
            const size_t o8 = o0 + (size_t)8 * MAXLEN * NCHD;
            out[o0]     = d[16][0] + bias[128 + oc];
            out[o0 + 1] = d[16][1] + bias[128 + oc + 1];
            out[o8]     = d[16][2] + bias[128 + oc];
            out[o8 + 1] = d[16][3] + bias[128 + oc + 1];
        }

        // ---- gate update + 8-way DSMEM broadcast of new h slice ----
        if (j < MAXLEN) {
            #pragma unroll
            for (int n = 0; n < 16; ++n) {
                float e0 = __shfl_xor_sync(0xffffffffu, d[n][0], 1);
                float e1 = __shfl_xor_sync(0xffffffffu, d[n][1], 1);
                float e2 = __shfl_xor_sync(0xffffffffu, d[n][2], 1);
                float e3 = __shfl_xor_sync(0xffffffffu, d[n][3], 1);
                float hvA = 0.f, hvB = 0.f;
                const int hc = 2 * n + (cc >> 1);
                if (!(cc & 1)) {
                    float rg = sigf(d[n][0] + bias[hc]);
                    float ug = sigf(d[n][1] + bias[32 + hc]);
                    float nn = tanha(fmaf(rg, e1 + bias[96 + hc], e0 + bias[64 + hc]));
                    float ho = h_s[wrow * 32 + hc];
                    hvA = fmaf(ug, ho - nn, nn);
                    rg = sigf(d[n][2] + bias[hc]);
                    ug = sigf(d[n][3] + bias[32 + hc]);
                    nn = tanha(fmaf(rg, e3 + bias[96 + hc], e2 + bias[64 + hc]));
                    ho = h_s[(wrow + 8) * 32 + hc];
                    hvB = fmaf(ug, ho - nn, nn);
                    h_s[wrow * 32 + hc]       = hvA;
                    h_s[(wrow + 8) * 32 + hc] = hvB;
                }
                // pack (hc=2n from cc0, hc=2n+1 from cc2) into u32 on cc==0 lanes
                float pA = __shfl_xor_sync(0xffffffffu, hvA, 2);
                float pB = __shfl_xor_sync(0xffffffffu, hvB, 2);
                if (cc == 0) {
                    uint32_t vA = (uint32_t)h_hi(hvA) | ((uint32_t)h_hi(pA) << 16);
                    uint32_t vB = (uint32_t)h_hi(hvB) | ((uint32_t)h_hi(pB) << 16);
                    const uint32_t offA = (uint32_t)((wrow * APITCH + s * 32 + 2 * n) * 2);
                    const uint32_t offB = (uint32_t)(((wrow + 8) * APITCH + s * 32 + 2 * n) * 2);
                    #pragma unroll
                    for (int r = 0; r < 8; ++r) {
                        asm volatile("st.shared::cluster.u32 [%0], %1;" :: "r"(pa[r] + offA), "r"(vA) : "memory");
                        asm volatile("st.shared::cluster.u32 [%0], %1;" :: "r"(pa[r] + offB), "r"(vB) : "memory");
                    }
                }
            }
        }

        CLUSTER_SYNC();   // new A planes visible cluster-wide
    }
}

// ---------------- launcher ----------------
extern "C" void kernel_launch(void* const* d_in, const int* in_sizes, int n_in,
                              void* d_out, int out_size) {
    const float* z     = (const float*)d_in[0];
    const float* xcond = (const float*)d_in[1];
    const float* W_lh  = (const float*)d_in[2];
    const float* b_lh  = (const float*)d_in[3];
    const float* W_ih  = (const float*)d_in[4];
    const float* W_hh  = (const float*)d_in[5];
    const float* b_ih  = (const float*)d_in[6];
    const float* b_hh  = (const float*)d_in[7];
    const float* W_out = (const float*)d_in[8];
    const float* b_out = (const float*)d_in[9];
    float* out = (float*)d_out;

    cudaFuncSetAttribute(gru_main_kernel, cudaFuncAttributeMaxDynamicSharedMemorySize, SMEM_DYN);

    prep_kernel<<<256, 256>>>(W_ih, W_hh, W_out, W_lh);
    pre_kernel<<<128, 256>>>(z, xcond, b_lh, b_ih, b_hh);
    gru_main_kernel<<<NBLK, NT, SMEM_DYN>>>(b_ih, b_hh, b_out, out);
}

// round 8
// speedup vs baseline: 3.6447x; 3.6447x over previous
#include <cuda_runtime.h>
#include <cuda_fp16.h>
#include <cstdint>

// ---------------- problem constants ----------------
#define BATCH   2048
#define RDIM    256
#define HIDD    256
#define CONDD   128
#define ZCD     384
#define NCHD    64
#define MAXLEN  128
#define NBLK    128            // 64 M-tiles x 2 N-halves
#define NT      256            // 8 warps
#define MROWS   32             // batch rows per CTA (pair shares them)
#define NTILES  68             // n8 tiles per CTA: 64 gate (128 hcols x 4) + 4 logit
#define KTILES  16
#define APITCH  264            // u16 pitch of A planes (conflict-free)

// streaming geometry: chunk = 2 ktiles
#define CH_U2      (2*NTILES*32)        // 4352 uint2
#define CH_BYTES   (CH_U2*8)            // 34816
#define NBUF       4
#define CHUNKS_PER_STEP 8
#define NCHUNK_TOT (MAXLEN*CHUNKS_PER_STEP)   // 1024

// dynamic smem layout (bytes)
#define OFF_WBUF 0
#define OFF_AHI  (NBUF*CH_BYTES)                   // 139264
#define OFF_ALO  (OFF_AHI + MROWS*APITCH*2)        // +16896
#define OFF_HS   (OFF_ALO + MROWS*APITCH*2)        // +16896
#define OFF_BIAS (OFF_HS + MROWS*128*4)            // +16384
#define SMEM_DYN (OFF_BIAS + 544*4 + 64)           // ~191.8KB

// ---------------- device-global scratch ----------------
__device__ __align__(16) uint2 g_bs[2 * KTILES * NTILES * 32];  // [half][kt][nt][lane], 557KB
__device__ float    g_h1[BATCH * RDIM];      // h after exact step 0
__device__ uint32_t g_stage[64 * 2 * 2 * (MROWS * 128)];  // [m][half][parity][row*128+hc], 4MB
__device__ int      g_flag[128];             // [m*2+half], reset by prep each launch
__device__ float    g_WhhT[RDIM * 768];
__device__ float    g_WlhT[ZCD * RDIM];

// ---------------- helpers ----------------
__device__ __forceinline__ float sigf(float x) { return 1.0f / (1.0f + __expf(-x)); }
__device__ __forceinline__ float tanha(float x) {
    float y; asm("tanh.approx.f32 %0, %1;" : "=f"(y) : "f"(x)); return y;
}
__device__ __forceinline__ uint16_t h_hi(float x) {
    __half h = __float2half_rn(x); return __half_as_ushort(h);
}
__device__ __forceinline__ uint16_t h_lo(float x) {
    __half h = __float2half_rn(x);
    return __half_as_ushort(__float2half_rn(x - __half2float(h)));
}
__device__ __forceinline__ uint32_t smem_u32(const void* p) {
    uint32_t a;
    asm("{ .reg .u64 t; cvta.to.shared.u64 t, %1; cvt.u32.u64 %0, t; }" : "=r"(a) : "l"(p));
    return a;
}
__device__ __forceinline__ void mbar_init(uint32_t m, uint32_t cnt) {
    asm volatile("mbarrier.init.shared.b64 [%0], %1;" :: "r"(m), "r"(cnt) : "memory");
}
__device__ __forceinline__ void mbar_expect_tx(uint32_t m, uint32_t bytes) {
    asm volatile("mbarrier.arrive.expect_tx.shared.b64 _, [%0], %1;" :: "r"(m), "r"(bytes) : "memory");
}
__device__ __forceinline__ void mbar_wait(uint32_t m, uint32_t parity) {
    asm volatile(
        "{\n\t.reg .pred P;\n\t"
        "W:\n\t"
        "mbarrier.try_wait.parity.acquire.cta.shared::cta.b64 P, [%0], %1, 0x989680;\n\t"
        "@P bra D;\n\t"
        "bra W;\n\t"
        "D:\n\t}"
        :: "r"(m), "r"(parity) : "memory");
}
__device__ __forceinline__ void bulk_g2s(uint32_t dst, const void* src, uint32_t bytes, uint32_t mbar) {
    asm volatile("cp.async.bulk.shared::cluster.global.mbarrier::complete_tx::bytes [%0], [%1], %2, [%3];"
                 :: "r"(dst), "l"(src), "r"(bytes), "r"(mbar) : "memory");
}
__device__ __forceinline__ void fence_proxy_async_cta() {
    asm volatile("fence.proxy.async.shared::cta;" ::: "memory");
}
__device__ __forceinline__ void flag_release(int* p, int v) {
    asm volatile("st.release.gpu.s32 [%0], %1;" :: "l"(p), "r"(v) : "memory");
}
__device__ __forceinline__ int flag_acquire(const int* p) {
    int v; asm volatile("ld.acquire.gpu.s32 %0, [%1];" : "=r"(v) : "l"(p) : "memory");
    return v;
}
// m16n8k16 row.col fp16 -> f32 accumulate (generic PTX)
__device__ __forceinline__ void mma16816(float* d, uint32_t a0, uint32_t a1, uint32_t a2, uint32_t a3,
                                         uint32_t b0, uint32_t b1) {
    asm volatile(
        "mma.sync.aligned.m16n8k16.row.col.f32.f16.f16.f32 "
        "{%0,%1,%2,%3}, {%4,%5,%6,%7}, {%8,%9}, {%0,%1,%2,%3};"
        : "+f"(d[0]), "+f"(d[1]), "+f"(d[2]), "+f"(d[3])
        : "r"(a0), "r"(a1), "r"(a2), "r"(a3), "r"(b0), "r"(b1));
}

// ---------------- prep: pack fp16 B-fragments + transposes + flag reset ----------------
__device__ __forceinline__ float wval_g(const float* Wih, const float* Whh, const float* Wout,
                                        int half, int nt, int q, int k) {
    if (nt < 64) {
        int col = nt * 8 + q;
        int hc  = half * 128 + (col >> 2);
        int g   = col & 3;
        if (g == 0) return Wih[hc*RDIM+k] + Whh[hc*RDIM+k];
        if (g == 1) return Wih[(256+hc)*RDIM+k] + Whh[(256+hc)*RDIM+k];
        if (g == 2) return Wih[(512+hc)*RDIM+k];
        return Whh[(512+hc)*RDIM+k];
    }
    int oc = half * 32 + (nt - 64) * 8 + q;
    return Wout[oc*RDIM + k];
}

__global__ void prep_kernel(const float* __restrict__ Wih,
                            const float* __restrict__ Whh,
                            const float* __restrict__ Wout,
                            const float* __restrict__ Wlh) {
    int i0 = blockIdx.x * blockDim.x + threadIdx.x;
    int stride = gridDim.x * blockDim.x;

    const int TOT = 2 * KTILES * NTILES * 32;   // 69632
    for (int idx = i0; idx < TOT; idx += stride) {
        int lane = idx & 31;
        int nt   = (idx >> 5) % NTILES;
        int kt   = (idx / (32 * NTILES)) % KTILES;
        int half = idx / (32 * NTILES * KTILES);
        int q    = lane >> 2;
        int c    = lane & 3;
        int k0   = kt * 16 + 2 * c;
        float w00 = wval_g(Wih, Whh, Wout, half, nt, q, k0);
        float w01 = wval_g(Wih, Whh, Wout, half, nt, q, k0 + 1);
        float w10 = wval_g(Wih, Whh, Wout, half, nt, q, k0 + 8);
        float w11 = wval_g(Wih, Whh, Wout, half, nt, q, k0 + 9);
        uint2 o;
        o.x = (uint32_t)h_hi(w00) | ((uint32_t)h_hi(w01) << 16);
        o.y = (uint32_t)h_hi(w10) | ((uint32_t)h_hi(w11) << 16);
        g_bs[idx] = o;
    }
    for (int idx = i0; idx < RDIM * 768; idx += stride) {
        int k = idx / 768, row = idx % 768;
        g_WhhT[idx] = Whh[row * RDIM + k];
    }
    for (int idx = i0; idx < ZCD * RDIM; idx += stride) {
        int k = idx >> 8, c = idx & 255;
        g_WlhT[idx] = Wlh[c * ZCD + k];
    }
    for (int idx = i0; idx < 128; idx += stride)
        g_flag[idx] = 0;
}

// ---------------- pre-kernel: h0 = Wlh [z,xc] + b ; h1 = GRU(0, h0) exact fp32 ----------------
__global__ void __launch_bounds__(256)
pre_kernel(const float* __restrict__ z, const float* __restrict__ xc,
           const float* __restrict__ blh, const float* __restrict__ bih,
           const float* __restrict__ bhh) {
    __shared__ __align__(16) float zc_s[16 * ZCD];
    __shared__ __align__(16) float h0_s[16 * RDIM];
    const int tid  = threadIdx.x;
    const int row0 = blockIdx.x * 16;

    for (int i = tid; i < 16 * HIDD; i += 256) {
        int r = i / HIDD, c = i % HIDD;
        zc_s[r * ZCD + c] = z[(row0 + r) * HIDD + c];
    }
    for (int i = tid; i < 16 * CONDD; i += 256) {
        int r = i / CONDD, c = i % CONDD;
        zc_s[r * ZCD + HIDD + c] = xc[(row0 + r) * CONDD + c];
    }
    __syncthreads();

    {
        float acc[16];
        float bv = blh[tid];
        #pragma unroll
        for (int r = 0; r < 16; ++r) acc[r] = bv;
        for (int k = 0; k < ZCD; ++k) {
            float w = g_WlhT[k * RDIM + tid];
            #pragma unroll
            for (int r = 0; r < 16; ++r)
                acc[r] = fmaf(zc_s[r * ZCD + k], w, acc[r]);
        }
        #pragma unroll
        for (int r = 0; r < 16; ++r) h0_s[r * RDIM + tid] = acc[r];
    }
    __syncthreads();

    float aR[16], aU[16], aH[16];
    #pragma unroll
    for (int r = 0; r < 16; ++r) { aR[r] = 0.f; aU[r] = 0.f; aH[r] = 0.f; }
    for (int k = 0; k < RDIM; ++k) {
        float wr = g_WhhT[k * 768 + tid];
        float wu = g_WhhT[k * 768 + 256 + tid];
        float wn = g_WhhT[k * 768 + 512 + tid];
        #pragma unroll
        for (int r = 0; r < 16; ++r) {
            float hv = h0_s[r * RDIM + k];
            aR[r] = fmaf(hv, wr, aR[r]);
            aU[r] = fmaf(hv, wu, aU[r]);
            aH[r] = fmaf(hv, wn, aH[r]);
        }
    }
    const float br = bih[tid] + bhh[tid];
    const float bu = bih[256 + tid] + bhh[256 + tid];
    const float bi = bih[512 + tid];
    const float bh = bhh[512 + tid];
    #pragma unroll
    for (int r = 0; r < 16; ++r) {
        float rg = sigf(aR[r] + br);
        float ug = sigf(aU[r] + bu);
        float nn = tanhf(fmaf(rg, aH[r] + bh, bi));
        g_h1[(row0 + r) * RDIM + tid] = fmaf(ug, h0_s[r * RDIM + tid] - nn, nn);
    }
}

// ---------------- main persistent pair-split kernel ----------------
__global__ void __launch_bounds__(NT, 1)
gru_main_kernel(const float* __restrict__ bih, const float* __restrict__ bhh,
                const float* __restrict__ bout, float* __restrict__ out) {
    extern __shared__ __align__(16) char smem[];
    uint2*    wbuf = reinterpret_cast<uint2*>(smem + OFF_WBUF);
    uint16_t* a_hi = reinterpret_cast<uint16_t*>(smem + OFF_AHI);
    uint16_t* a_lo = reinterpret_cast<uint16_t*>(smem + OFF_ALO);
    float*    h_s  = reinterpret_cast<float*>(smem + OFF_HS);
    float*    bias = reinterpret_cast<float*>(smem + OFF_BIAS);
    __shared__ __align__(16) unsigned long long mbars[NBUF];

    const int tid  = threadIdx.x;
    const int wid  = tid >> 5;
    const int lane = tid & 31;
    const int cc   = lane & 3;
    const int gID  = lane >> 2;
    const int m    = blockIdx.x >> 1;
    const int half = blockIdx.x & 1;
    const int row0 = m * MROWS;
    const int rowA = (wid & 1) * 16 + gID;   // warp's m16 tile base row + gID
    const int ntbase = (wid >> 1) * 17;

    uint32_t mb[NBUF];
    #pragma unroll
    for (int b = 0; b < NBUF; ++b) mb[b] = smem_u32(&mbars[b]);
    if (tid < NBUF) mbar_init(mb[tid], 1);

    // biases (local to this CTA's 128 hcols + 32 logit cols)
    if (tid < 128) {
        int H = half * 128 + tid;
        bias[tid]       = bih[H] + bhh[H];
        bias[128 + tid] = bih[256 + H] + bhh[256 + H];
        bias[256 + tid] = bih[512 + H];
        bias[384 + tid] = bhh[512 + H];
    }
    if (tid < 32) bias[512 + tid] = bout[half * 32 + tid];

    // A planes (fp16 hi/lo of h1, all 256 cols) + own fp32 half
    for (int i = tid; i < MROWS * RDIM; i += NT) {
        int r = i >> 8, k = i & 255;
        float v = g_h1[(row0 + r) * RDIM + k];
        a_hi[r * APITCH + k] = h_hi(v);
        a_lo[r * APITCH + k] = h_lo(v);
    }
    for (int i = tid; i < MROWS * 128; i += NT) {
        int r = i >> 7, c = i & 127;
        h_s[i] = g_h1[(row0 + r) * RDIM + half * 128 + c];
    }
    __syncthreads();

    // kick off 4 chunks
    const uint2* wsrc = g_bs + (size_t)half * (KTILES * NTILES * 32);
    if (tid == 0) {
        fence_proxy_async_cta();
        #pragma unroll
        for (int q = 0; q < NBUF; ++q) {
            mbar_expect_tx(mb[q], CH_BYTES);
            bulk_g2s(smem_u32(wbuf + q * CH_U2), wsrc + q * CH_U2, CH_BYTES, mb[q]);
        }
    }

    int* my_flag   = &g_flag[m * 2 + half];
    int* peer_flag = &g_flag[m * 2 + (half ^ 1)];
    int cglob = 0;

    #pragma unroll 1
    for (int j = 1; j <= MAXLEN; ++j) {
        float d[17][4];
        #pragma unroll
        for (int n = 0; n < 17; ++n) { d[n][0]=0.f; d[n][1]=0.f; d[n][2]=0.f; d[n][3]=0.f; }

        // ---- K loop: 8 chunks of 2 ktiles ----
        #pragma unroll 1
        for (int ck = 0; ck < CHUNKS_PER_STEP; ++ck, ++cglob) {
            const int buf = cglob & 3;
            mbar_wait(mb[buf], (cglob >> 2) & 1);
            const uint2* bp = wbuf + buf * CH_U2;

            #pragma unroll
            for (int k2 = 0; k2 < 2; ++k2) {
                const int k0 = (ck * 2 + k2) * 16 + 2 * cc;
                uint32_t ah0 = *reinterpret_cast<const uint32_t*>(a_hi + rowA * APITCH + k0);
                uint32_t ah1 = *reinterpret_cast<const uint32_t*>(a_hi + (rowA + 8) * APITCH + k0);
                uint32_t ah2 = *reinterpret_cast<const uint32_t*>(a_hi + rowA * APITCH + k0 + 8);
                uint32_t ah3 = *reinterpret_cast<const uint32_t*>(a_hi + (rowA + 8) * APITCH + k0 + 8);
                uint32_t al0 = *reinterpret_cast<const uint32_t*>(a_lo + rowA * APITCH + k0);
                uint32_t al1 = *reinterpret_cast<const uint32_t*>(a_lo + (rowA + 8) * APITCH + k0);
                uint32_t al2 = *reinterpret_cast<const uint32_t*>(a_lo + rowA * APITCH + k0 + 8);
                uint32_t al3 = *reinterpret_cast<const uint32_t*>(a_lo + (rowA + 8) * APITCH + k0 + 8);
                #pragma unroll
                for (int n = 0; n < 17; ++n) {
                    uint2 B = bp[(k2 * NTILES + ntbase + n) * 32 + lane];
                    mma16816(d[n], ah0, ah1, ah2, ah3, B.x, B.y);
                    mma16816(d[n], al0, al1, al2, al3, B.x, B.y);
                }
            }
            __syncthreads();
            if (tid == 0 && cglob + NBUF < NCHUNK_TOT) {
                mbar_expect_tx(mb[buf], CH_BYTES);
                bulk_g2s(smem_u32(wbuf + buf * CH_U2),
                         wsrc + ((cglob + NBUF) & 7) * CH_U2, CH_BYTES, mb[buf]);
            }
        }

        // ---- epilogue ----
        uint32_t* stg_w = g_stage + (((size_t)(m * 2 + half) * 2 + (j & 1)) << 12);
        #pragma unroll
        for (int n = 0; n < 17; ++n) {
            const int nt = ntbase + n;
            if (nt < 64) {
                if (j < MAXLEN) {
                    float e0 = __shfl_xor_sync(0xffffffffu, d[n][0], 1);
                    float e1 = __shfl_xor_sync(0xffffffffu, d[n][1], 1);
                    float e2 = __shfl_xor_sync(0xffffffffu, d[n][2], 1);
                    float e3 = __shfl_xor_sync(0xffffffffu, d[n][3], 1);
                    if (!(cc & 1)) {
                        const int hc = nt * 2 + ((lane & 2) >> 1);   // local hcol 0..127
                        // row rowA
                        float rg = sigf(d[n][0] + bias[hc]);
                        float ug = sigf(d[n][1] + bias[128 + hc]);
                        float nn = tanha(fmaf(rg, e1 + bias[384 + hc], e0 + bias[256 + hc]));
                        float ho = h_s[rowA * 128 + hc];
                        float hvA = fmaf(ug, ho - nn, nn);
                        // row rowA + 8
                        rg = sigf(d[n][2] + bias[hc]);
                        ug = sigf(d[n][3] + bias[128 + hc]);
                        nn = tanha(fmaf(rg, e3 + bias[384 + hc], e2 + bias[256 + hc]));
                        ho = h_s[(rowA + 8) * 128 + hc];
                        float hvB = fmaf(ug, ho - nn, nn);

                        h_s[rowA * 128 + hc]       = hvA;
                        h_s[(rowA + 8) * 128 + hc] = hvB;
                        uint16_t hA = h_hi(hvA), lA = h_lo(hvA);
                        uint16_t hB = h_hi(hvB), lB = h_lo(hvB);
                        a_hi[rowA * APITCH + half * 128 + hc]       = hA;
                        a_lo[rowA * APITCH + half * 128 + hc]       = lA;
                        a_hi[(rowA + 8) * APITCH + half * 128 + hc] = hB;
                        a_lo[(rowA + 8) * APITCH + half * 128 + hc] = lB;
                        __stcg(&stg_w[rowA * 128 + hc],       (uint32_t)hA | ((uint32_t)lA << 16));
                        __stcg(&stg_w[(rowA + 8) * 128 + hc], (uint32_t)hB | ((uint32_t)lB << 16));
                    }
                }
            } else {
                const int loc = (nt - 64) * 8 + 2 * cc;
                const int oc  = half * 32 + loc;
                const size_t o0 = ((size_t)(row0 + rowA) * MAXLEN + (j - 1)) * NCHD + oc;
                const size_t o8 = o0 + (size_t)8 * MAXLEN * NCHD;
                out[o0]     = d[n][0] + bias[512 + loc];
                out[o0 + 1] = d[n][1] + bias[512 + loc + 1];
                out[o8]     = d[n][2] + bias[512 + loc];
                out[o8 + 1] = d[n][3] + bias[512 + loc + 1];
            }
        }

        // ---- pair exchange of new h half ----
        if (j < MAXLEN) {
            __syncthreads();                       // all staging/smem writes done
            if (tid == 0) {
                flag_release(my_flag, j);
                while (flag_acquire(peer_flag) < j) { }
            }
            __syncthreads();                       // acquire visible CTA-wide
            const uint32_t* stg_r = g_stage + (((size_t)(m * 2 + (half ^ 1)) * 2 + (j & 1)) << 12);
            #pragma unroll
            for (int i = 0; i < 16; ++i) {
                int idx = tid + i * NT;
                uint32_t v = __ldcg(&stg_r[idx]);
                int r = idx >> 7, c = idx & 127;
                a_hi[r * APITCH + (half ^ 1) * 128 + c] = (uint16_t)(v & 0xffffu);
                a_lo[r * APITCH + (half ^ 1) * 128 + c] = (uint16_t)(v >> 16);
            }
            __syncthreads();                       // A planes complete before next GEMM
        }
    }
}

// ---------------- launcher ----------------
extern "C" void kernel_launch(void* const* d_in, const int* in_sizes, int n_in,
                              void* d_out, int out_size) {
    const float* z     = (const float*)d_in[0];
    const float* xcond = (const float*)d_in[1];
    const float* W_lh  = (const float*)d_in[2];
    const float* b_lh  = (const float*)d_in[3];
    const float* W_ih  = (const float*)d_in[4];
    const float* W_hh  = (const float*)d_in[5];
    const float* b_ih  = (const float*)d_in[6];
    const float* b_hh  = (const float*)d_in[7];
    const float* W_out = (const float*)d_in[8];
    const float* b_out = (const float*)d_in[9];
    float* out = (float*)d_out;

    cudaFuncSetAttribute(gru_main_kernel, cudaFuncAttributeMaxDynamicSharedMemorySize, SMEM_DYN);

    prep_kernel<<<256, 256>>>(W_ih, W_hh, W_out, W_lh);
    pre_kernel<<<128, 256>>>(z, xcond, b_lh, b_ih, b_hh);
    gru_main_kernel<<<NBLK, NT, SMEM_DYN>>>(b_ih, b_hh, b_out, out);
}

// round 9
// speedup vs baseline: 3.9612x; 1.0868x over previous
#include <cuda_runtime.h>
#include <cuda_fp16.h>
#include <cstdint>

// ---------------- problem constants ----------------
#define BATCH   2048
#define RDIM    256
#define HIDD    256
#define CONDD   128
#define ZCD     384
#define NCHD    64
#define MAXLEN  128
#define NBLK    128            // 64 M-tiles x 2 N-halves
#define NT      256            // 8 warps
#define MROWS   32             // batch rows per CTA (pair shares them)
#define NTILES  68             // n8 tiles per CTA: 64 gate (128 hcols x 4) + 4 logit
#define KTILES  16
#define APITCH  264            // u16 pitch of A planes (conflict-free)

// streaming geometry: chunk = 2 ktiles
#define CH_U2      (2*NTILES*32)        // 4352 uint2
#define CH_BYTES   (CH_U2*8)            // 34816
#define NBUF       4
#define CHUNKS_PER_STEP 8
#define NCHUNK_TOT (MAXLEN*CHUNKS_PER_STEP)

// dynamic smem layout (bytes)
#define OFF_WBUF 0
#define OFF_AHI  (NBUF*CH_BYTES)
#define OFF_ALO  (OFF_AHI + MROWS*APITCH*2)
#define OFF_HS   (OFF_ALO + MROWS*APITCH*2)
#define OFF_BIAS (OFF_HS + MROWS*128*4)
#define SMEM_DYN (OFF_BIAS + 544*4 + 64)

// ---------------- device-global scratch ----------------
__device__ __align__(16) uint2 g_bs[2 * KTILES * NTILES * 32];   // [half][kt][nt][lane] (permuted k)
__device__ float    g_h1[BATCH * RDIM];
__device__ uint32_t g_stage[64 * 2 * 2 * (MROWS * 128)];          // [m][half][parity][row*128+hc]
__device__ int      g_flag[128];
__device__ float    g_WhhT[RDIM * 768];
__device__ float    g_WlhT[ZCD * RDIM];

// ---------------- helpers ----------------
__device__ __forceinline__ float sigf(float x) { return 1.0f / (1.0f + __expf(-x)); }
__device__ __forceinline__ float tanha(float x) {
    float y; asm("tanh.approx.f32 %0, %1;" : "=f"(y) : "f"(x)); return y;
}
__device__ __forceinline__ uint16_t h_hi(float x) {
    __half h = __float2half_rn(x); return __half_as_ushort(h);
}
__device__ __forceinline__ uint16_t h_lo(float x) {
    __half h = __float2half_rn(x);
    return __half_as_ushort(__float2half_rn(x - __half2float(h)));
}
__device__ __forceinline__ uint32_t smem_u32(const void* p) {
    uint32_t a;
    asm("{ .reg .u64 t; cvta.to.shared.u64 t, %1; cvt.u32.u64 %0, t; }" : "=r"(a) : "l"(p));
    return a;
}
__device__ __forceinline__ void mbar_init(uint32_t m, uint32_t cnt) {
    asm volatile("mbarrier.init.shared.b64 [%0], %1;" :: "r"(m), "r"(cnt) : "memory");
}
__device__ __forceinline__ void mbar_expect_tx(uint32_t m, uint32_t bytes) {
    asm volatile("mbarrier.arrive.expect_tx.shared.b64 _, [%0], %1;" :: "r"(m), "r"(bytes) : "memory");
}
__device__ __forceinline__ void mbar_wait(uint32_t m, uint32_t parity) {
    asm volatile(
        "{\n\t.reg .pred P;\n\t"
        "W:\n\t"
        "mbarrier.try_wait.parity.acquire.cta.shared::cta.b64 P, [%0], %1, 0x989680;\n\t"
        "@P bra D;\n\t"
        "bra W;\n\t"
        "D:\n\t}"
        :: "r"(m), "r"(parity) : "memory");
}
__device__ __forceinline__ void bulk_g2s(uint32_t dst, const void* src, uint32_t bytes, uint32_t mbar) {
    asm volatile("cp.async.bulk.shared::cluster.global.mbarrier::complete_tx::bytes [%0], [%1], %2, [%3];"
                 :: "r"(dst), "l"(src), "r"(bytes), "r"(mbar) : "memory");
}
__device__ __forceinline__ void fence_proxy_async_cta() {
    asm volatile("fence.proxy.async.shared::cta;" ::: "memory");
}
__device__ __forceinline__ void flag_release(int* p, int v) {
    asm volatile("st.release.gpu.s32 [%0], %1;" :: "l"(p), "r"(v) : "memory");
}
__device__ __forceinline__ int flag_acquire(const int* p) {
    int v; asm volatile("ld.acquire.gpu.s32 %0, [%1];" : "=r"(v) : "l"(p) : "memory");
    return v;
}
__device__ __forceinline__ void mma16816(float* d, uint32_t a0, uint32_t a1, uint32_t a2, uint32_t a3,
                                         uint32_t b0, uint32_t b1) {
    asm volatile(
        "mma.sync.aligned.m16n8k16.row.col.f32.f16.f16.f32 "
        "{%0,%1,%2,%3}, {%4,%5,%6,%7}, {%8,%9}, {%0,%1,%2,%3};"
        : "+f"(d[0]), "+f"(d[1]), "+f"(d[2]), "+f"(d[3])
        : "r"(a0), "r"(a1), "r"(a2), "r"(a3), "r"(b0), "r"(b1));
}

// ---------------- prep: pack fp16 B-fragments (own-half-first k order) ----------------
__device__ __forceinline__ float wval_g(const float* Wih, const float* Whh, const float* Wout,
                                        int half, int nt, int q, int kp) {
    // permuted k -> real k: own half first
    int k = (kp < 128) ? (half * 128 + kp) : ((half ^ 1) * 128 + (kp - 128));
    if (nt < 64) {
        int col = nt * 8 + q;
        int hc  = half * 128 + (col >> 2);
        int g   = col & 3;
        if (g == 0) return Wih[hc*RDIM+k] + Whh[hc*RDIM+k];
        if (g == 1) return Wih[(256+hc)*RDIM+k] + Whh[(256+hc)*RDIM+k];
        if (g == 2) return Wih[(512+hc)*RDIM+k];
        return Whh[(512+hc)*RDIM+k];
    }
    int oc = half * 32 + (nt - 64) * 8 + q;
    return Wout[oc*RDIM + k];
}

__global__ void prep_kernel(const float* __restrict__ Wih,
                            const float* __restrict__ Whh,
                            const float* __restrict__ Wout,
                            const float* __restrict__ Wlh) {
    int i0 = blockIdx.x * blockDim.x + threadIdx.x;
    int stride = gridDim.x * blockDim.x;

    const int TOT = 2 * KTILES * NTILES * 32;
    for (int idx = i0; idx < TOT; idx += stride) {
        int lane = idx & 31;
        int nt   = (idx >> 5) % NTILES;
        int kt   = (idx / (32 * NTILES)) % KTILES;
        int half = idx / (32 * NTILES * KTILES);
        int q    = lane >> 2;
        int c    = lane & 3;
        int k0   = kt * 16 + 2 * c;
        float w00 = wval_g(Wih, Whh, Wout, half, nt, q, k0);
        float w01 = wval_g(Wih, Whh, Wout, half, nt, q, k0 + 1);
        float w10 = wval_g(Wih, Whh, Wout, half, nt, q, k0 + 8);
        float w11 = wval_g(Wih, Whh, Wout, half, nt, q, k0 + 9);
        uint2 o;
        o.x = (uint32_t)h_hi(w00) | ((uint32_t)h_hi(w01) << 16);
        o.y = (uint32_t)h_hi(w10) | ((uint32_t)h_hi(w11) << 16);
        g_bs[idx] = o;
    }
    for (int idx = i0; idx < RDIM * 768; idx += stride) {
        int k = idx / 768, row = idx % 768;
        g_WhhT[idx] = Whh[row * RDIM + k];
    }
    for (int idx = i0; idx < ZCD * RDIM; idx += stride) {
        int k = idx >> 8, c = idx & 255;
        g_WlhT[idx] = Wlh[c * ZCD + k];
    }
    for (int idx = i0; idx < 128; idx += stride)
        g_flag[idx] = 0;
}

// ---------------- pre-kernel: exact fp32 h0 + step-0 GRU -> g_h1 ----------------
__global__ void __launch_bounds__(256)
pre_kernel(const float* __restrict__ z, const float* __restrict__ xc,
           const float* __restrict__ blh, const float* __restrict__ bih,
           const float* __restrict__ bhh) {
    __shared__ __align__(16) float zc_s[16 * ZCD];
    __shared__ __align__(16) float h0_s[16 * RDIM];
    const int tid  = threadIdx.x;
    const int row0 = blockIdx.x * 16;

    for (int i = tid; i < 16 * HIDD; i += 256) {
        int r = i / HIDD, c = i % HIDD;
        zc_s[r * ZCD + c] = z[(row0 + r) * HIDD + c];
    }
    for (int i = tid; i < 16 * CONDD; i += 256) {
        int r = i / CONDD, c = i % CONDD;
        zc_s[r * ZCD + HIDD + c] = xc[(row0 + r) * CONDD + c];
    }
    __syncthreads();

    {
        float acc[16];
        float bv = blh[tid];
        #pragma unroll
        for (int r = 0; r < 16; ++r) acc[r] = bv;
        for (int k = 0; k < ZCD; ++k) {
            float w = g_WlhT[k * RDIM + tid];
            #pragma unroll
            for (int r = 0; r < 16; ++r)
                acc[r] = fmaf(zc_s[r * ZCD + k], w, acc[r]);
        }
        #pragma unroll
        for (int r = 0; r < 16; ++r) h0_s[r * RDIM + tid] = acc[r];
    }
    __syncthreads();

    float aR[16], aU[16], aH[16];
    #pragma unroll
    for (int r = 0; r < 16; ++r) { aR[r] = 0.f; aU[r] = 0.f; aH[r] = 0.f; }
    for (int k = 0; k < RDIM; ++k) {
        float wr = g_WhhT[k * 768 + tid];
        float wu = g_WhhT[k * 768 + 256 + tid];
        float wn = g_WhhT[k * 768 + 512 + tid];
        #pragma unroll
        for (int r = 0; r < 16; ++r) {
            float hv = h0_s[r * RDIM + k];
            aR[r] = fmaf(hv, wr, aR[r]);
            aU[r] = fmaf(hv, wu, aU[r]);
            aH[r] = fmaf(hv, wn, aH[r]);
        }
    }
    const float br = bih[tid] + bhh[tid];
    const float bu = bih[256 + tid] + bhh[256 + tid];
    const float bi = bih[512 + tid];
    const float bh = bhh[512 + tid];
    #pragma unroll
    for (int r = 0; r < 16; ++r) {
        float rg = sigf(aR[r] + br);
        float ug = sigf(aU[r] + bu);
        float nn = tanhf(fmaf(rg, aH[r] + bh, bi));
        g_h1[(row0 + r) * RDIM + tid] = fmaf(ug, h0_s[r * RDIM + tid] - nn, nn);
    }
}

// ---------------- main persistent pair-split kernel (own-first K, slack exchange) ----------------
__global__ void __launch_bounds__(NT, 1)
gru_main_kernel(const float* __restrict__ bih, const float* __restrict__ bhh,
                const float* __restrict__ bout, float* __restrict__ out) {
    extern __shared__ __align__(16) char smem[];
    uint2*    wbuf = reinterpret_cast<uint2*>(smem + OFF_WBUF);
    uint16_t* a_hi = reinterpret_cast<uint16_t*>(smem + OFF_AHI);
    uint16_t* a_lo = reinterpret_cast<uint16_t*>(smem + OFF_ALO);
    float*    h_s  = reinterpret_cast<float*>(smem + OFF_HS);
    float*    bias = reinterpret_cast<float*>(smem + OFF_BIAS);
    __shared__ __align__(16) unsigned long long mbars[NBUF];

    const int tid  = threadIdx.x;
    const int wid  = tid >> 5;
    const int lane = tid & 31;
    const int cc   = lane & 3;
    const int gID  = lane >> 2;
    const int m    = blockIdx.x >> 1;
    const int half = blockIdx.x & 1;
    const int row0 = m * MROWS;
    const int rowA = (wid & 1) * 16 + gID;
    const int ntbase = (wid >> 1) * 17;

    uint32_t mb[NBUF];
    #pragma unroll
    for (int b = 0; b < NBUF; ++b) mb[b] = smem_u32(&mbars[b]);
    if (tid < NBUF) mbar_init(mb[tid], 1);

    if (tid < 128) {
        int H = half * 128 + tid;
        bias[tid]       = bih[H] + bhh[H];
        bias[128 + tid] = bih[256 + H] + bhh[256 + H];
        bias[256 + tid] = bih[512 + H];
        bias[384 + tid] = bhh[512 + H];
    }
    if (tid < 32) bias[512 + tid] = bout[half * 32 + tid];

    // A planes in PERMUTED column order: cols [0,128)=own half, [128,256)=peer half
    for (int i = tid; i < MROWS * RDIM; i += NT) {
        int r = i >> 8, kp = i & 255;
        int k = (kp < 128) ? (half * 128 + kp) : ((half ^ 1) * 128 + (kp - 128));
        float v = g_h1[(row0 + r) * RDIM + k];
        a_hi[r * APITCH + kp] = h_hi(v);
        a_lo[r * APITCH + kp] = h_lo(v);
    }
    for (int i = tid; i < MROWS * 128; i += NT) {
        int r = i >> 7, c = i & 127;
        h_s[i] = g_h1[(row0 + r) * RDIM + half * 128 + c];
    }
    __syncthreads();

    const uint2* wsrc = g_bs + (size_t)half * (KTILES * NTILES * 32);
    if (tid == 0) {
        fence_proxy_async_cta();
        #pragma unroll
        for (int q = 0; q < NBUF; ++q) {
            mbar_expect_tx(mb[q], CH_BYTES);
            bulk_g2s(smem_u32(wbuf + q * CH_U2), wsrc + q * CH_U2, CH_BYTES, mb[q]);
        }
    }

    int* my_flag   = &g_flag[m * 2 + half];
    int* peer_flag = &g_flag[m * 2 + (half ^ 1)];
    int cglob = 0;

    #pragma unroll 1
    for (int j = 1; j <= MAXLEN; ++j) {
        float d[17][4];
        #pragma unroll
        for (int n = 0; n < 17; ++n) { d[n][0]=0.f; d[n][1]=0.f; d[n][2]=0.f; d[n][3]=0.f; }

        // ---- K phase 1: chunks 0-3 (OWN-half k columns, locally fresh) ----
        #pragma unroll 1
        for (int ck = 0; ck < 4; ++ck, ++cglob) {
            const int buf = cglob & 3;
            mbar_wait(mb[buf], (cglob >> 2) & 1);
            const uint2* bp = wbuf + buf * CH_U2;
            #pragma unroll
            for (int k2 = 0; k2 < 2; ++k2) {
                const int k0 = (ck * 2 + k2) * 16 + 2 * cc;
                uint32_t ah0 = *reinterpret_cast<const uint32_t*>(a_hi + rowA * APITCH + k0);
                uint32_t ah1 = *reinterpret_cast<const uint32_t*>(a_hi + (rowA + 8) * APITCH + k0);
                uint32_t ah2 = *reinterpret_cast<const uint32_t*>(a_hi + rowA * APITCH + k0 + 8);
                uint32_t ah3 = *reinterpret_cast<const uint32_t*>(a_hi + (rowA + 8) * APITCH + k0 + 8);
                uint32_t al0 = *reinterpret_cast<const uint32_t*>(a_lo + rowA * APITCH + k0);
                uint32_t al1 = *reinterpret_cast<const uint32_t*>(a_lo + (rowA + 8) * APITCH + k0);
                uint32_t al2 = *reinterpret_cast<const uint32_t*>(a_lo + rowA * APITCH + k0 + 8);
                uint32_t al3 = *reinterpret_cast<const uint32_t*>(a_lo + (rowA + 8) * APITCH + k0 + 8);
                #pragma unroll
                for (int n = 0; n < 17; ++n) {
                    uint2 B = bp[(k2 * NTILES + ntbase + n) * 32 + lane];
                    mma16816(d[n], ah0, ah1, ah2, ah3, B.x, B.y);
                    mma16816(d[n], al0, al1, al2, al3, B.x, B.y);
                }
            }
            __syncthreads();
            if (tid == 0 && cglob + NBUF < NCHUNK_TOT) {
                mbar_expect_tx(mb[buf], CH_BYTES);
                bulk_g2s(smem_u32(wbuf + buf * CH_U2),
                         wsrc + ((cglob + NBUF) & 7) * CH_U2, CH_BYTES, mb[buf]);
            }
        }

        // ---- exchange: install peer's h_j into A cols [128,256) (one full step of slack) ----
        if (j >= 2) {
            if (tid == 0) {
                while (flag_acquire(peer_flag) < j - 1) { }
            }
            __syncthreads();
            const uint4* stg_r = reinterpret_cast<const uint4*>(
                g_stage + (((size_t)(m * 2 + (half ^ 1)) * 2 + ((j - 1) & 1)) << 12));
            #pragma unroll
            for (int i = 0; i < 4; ++i) {
                int idx = tid + i * NT;                 // uint4 index: 4 values
                uint4 v = __ldcg(&stg_r[idx]);
                int r = idx >> 5, c4 = (idx & 31) * 4;  // 32 uint4 per row
                uint16_t* ph = a_hi + r * APITCH + 128 + c4;
                uint16_t* pl = a_lo + r * APITCH + 128 + c4;
                ph[0] = (uint16_t)(v.x & 0xffffu); pl[0] = (uint16_t)(v.x >> 16);
                ph[1] = (uint16_t)(v.y & 0xffffu); pl[1] = (uint16_t)(v.y >> 16);
                ph[2] = (uint16_t)(v.z & 0xffffu); pl[2] = (uint16_t)(v.z >> 16);
                ph[3] = (uint16_t)(v.w & 0xffffu); pl[3] = (uint16_t)(v.w >> 16);
            }
            __syncthreads();
        }

        // ---- K phase 2: chunks 4-7 (PEER-half k columns) ----
        #pragma unroll 1
        for (int ck = 4; ck < 8; ++ck, ++cglob) {
            const int buf = cglob & 3;
            mbar_wait(mb[buf], (cglob >> 2) & 1);
            const uint2* bp = wbuf + buf * CH_U2;
            #pragma unroll
            for (int k2 = 0; k2 < 2; ++k2) {
                const int k0 = (ck * 2 + k2) * 16 + 2 * cc;
                uint32_t ah0 = *reinterpret_cast<const uint32_t*>(a_hi + rowA * APITCH + k0);
                uint32_t ah1 = *reinterpret_cast<const uint32_t*>(a_hi + (rowA + 8) * APITCH + k0);
                uint32_t ah2 = *reinterpret_cast<const uint32_t*>(a_hi + rowA * APITCH + k0 + 8);
                uint32_t ah3 = *reinterpret_cast<const uint32_t*>(a_hi + (rowA + 8) * APITCH + k0 + 8);
                uint32_t al0 = *reinterpret_cast<const uint32_t*>(a_lo + rowA * APITCH + k0);
                uint32_t al1 = *reinterpret_cast<const uint32_t*>(a_lo + (rowA + 8) * APITCH + k0);
                uint32_t al2 = *reinterpret_cast<const uint32_t*>(a_lo + rowA * APITCH + k0 + 8);
                uint32_t al3 = *reinterpret_cast<const uint32_t*>(a_lo + (rowA + 8) * APITCH + k0 + 8);
                #pragma unroll
                for (int n = 0; n < 17; ++n) {
                    uint2 B = bp[(k2 * NTILES + ntbase + n) * 32 + lane];
                    mma16816(d[n], ah0, ah1, ah2, ah3, B.x, B.y);
                    mma16816(d[n], al0, al1, al2, al3, B.x, B.y);
                }
            }
            __syncthreads();
            if (tid == 0 && cglob + NBUF < NCHUNK_TOT) {
                mbar_expect_tx(mb[buf], CH_BYTES);
                bulk_g2s(smem_u32(wbuf + buf * CH_U2),
                         wsrc + ((cglob + NBUF) & 7) * CH_U2, CH_BYTES, mb[buf]);
            }
        }

        // ---- epilogue: gates -> new own h, logits(j-1), staging write, flag release ----
        uint32_t* stg_w = g_stage + (((size_t)(m * 2 + half) * 2 + (j & 1)) << 12);
        #pragma unroll
        for (int n = 0; n < 17; ++n) {
            const int nt = ntbase + n;
            if (nt < 64) {
                if (j < MAXLEN) {
                    float e0 = __shfl_xor_sync(0xffffffffu, d[n][0], 1);
                    float e1 = __shfl_xor_sync(0xffffffffu, d[n][1], 1);
                    float e2 = __shfl_xor_sync(0xffffffffu, d[n][2], 1);
                    float e3 = __shfl_xor_sync(0xffffffffu, d[n][3], 1);
                    if (!(cc & 1)) {
                        const int hc = nt * 2 + ((lane & 2) >> 1);   // local hcol 0..127
                        float rg = sigf(d[n][0] + bias[hc]);
                        float ug = sigf(d[n][1] + bias[128 + hc]);
                        float nn = tanha(fmaf(rg, e1 + bias[384 + hc], e0 + bias[256 + hc]));
                        float ho = h_s[rowA * 128 + hc];
                        float hvA = fmaf(ug, ho - nn, nn);
                        rg = sigf(d[n][2] + bias[hc]);
                        ug = sigf(d[n][3] + bias[128 + hc]);
                        nn = tanha(fmaf(rg, e3 + bias[384 + hc], e2 + bias[256 + hc]));
                        ho = h_s[(rowA + 8) * 128 + hc];
                        float hvB = fmaf(ug, ho - nn, nn);

                        h_s[rowA * 128 + hc]       = hvA;
                        h_s[(rowA + 8) * 128 + hc] = hvB;
                        uint16_t hA = h_hi(hvA), lA = h_lo(hvA);
                        uint16_t hB = h_hi(hvB), lB = h_lo(hvB);
                        // own half lives in A cols [0,128) (permuted layout)
                        a_hi[rowA * APITCH + hc]       = hA;
                        a_lo[rowA * APITCH + hc]       = lA;
                        a_hi[(rowA + 8) * APITCH + hc] = hB;
                        a_lo[(rowA + 8) * APITCH + hc] = lB;
                        __stcg(&stg_w[rowA * 128 + hc],       (uint32_t)hA | ((uint32_t)lA << 16));
                        __stcg(&stg_w[(rowA + 8) * 128 + hc], (uint32_t)hB | ((uint32_t)lB << 16));
                    }
                }
            } else {
                const int loc = (nt - 64) * 8 + 2 * cc;
                const int oc  = half * 32 + loc;
                const size_t o0 = ((size_t)(row0 + rowA) * MAXLEN + (j - 1)) * NCHD + oc;
                const size_t o8 = o0 + (size_t)8 * MAXLEN * NCHD;
                out[o0]     = d[n][0] + bias[512 + loc];
                out[o0 + 1] = d[n][1] + bias[512 + loc + 1];
                out[o8]     = d[n][2] + bias[512 + loc];
                out[o8 + 1] = d[n][3] + bias[512 + loc + 1];
            }
        }
        __syncthreads();                 // own A cols + staging complete
        if (j < MAXLEN && tid == 0)
            flag_release(my_flag, j);    // publish h_{j+1} own half
    }
}

// ---------------- launcher ----------------
extern "C" void kernel_launch(void* const* d_in, const int* in_sizes, int n_in,
                              void* d_out, int out_size) {
    const float* z     = (const float*)d_in[0];
    const float* xcond = (const float*)d_in[1];
    const float* W_lh  = (const float*)d_in[2];
    const float* b_lh  = (const float*)d_in[3];
    const float* W_ih  = (const float*)d_in[4];
    const float* W_hh  = (const float*)d_in[5];
    const float* b_ih  = (const float*)d_in[6];
    const float* b_hh  = (const float*)d_in[7];
    const float* W_out = (const float*)d_in[8];
    const float* b_out = (const float*)d_in[9];
    float* out = (float*)d_out;

    cudaFuncSetAttribute(gru_main_kernel, cudaFuncAttributeMaxDynamicSharedMemorySize, SMEM_DYN);

    prep_kernel<<<256, 256>>>(W_ih, W_hh, W_out, W_lh);
    pre_kernel<<<128, 256>>>(z, xcond, b_lh, b_ih, b_hh);
    gru_main_kernel<<<NBLK, NT, SMEM_DYN>>>(b_ih, b_hh, b_out, out);
}

// round 10
// speedup vs baseline: 4.3111x; 1.0883x over previous
#include <cuda_runtime.h>
#include <cuda_fp16.h>
#include <cstdint>

// ---------------- problem constants ----------------
#define BATCH   2048
#define RDIM    256
#define HIDD    256
#define CONDD   128
#define ZCD     384
#define NCHD    64
#define MAXLEN  128
#define NBLK    128            // 32 M-tiles x 4 N-quarters
#define NT      256            // 8 warps
#define MROWS   64             // batch rows per CTA (quartet shares them)
#define NTILES  34             // n8 tiles per CTA: 32 gate (64 hcols x 4) + 2 logit
#define KTILES  16
#define APITCH  264            // u16 pitch of A planes (conflict-free)

#define W_U2    (KTILES*NTILES*32)     // 17408 uint2 = 139264 B
// dynamic smem layout (bytes)
#define OFF_W    0
#define OFF_AHI  139264
#define OFF_ALO  (OFF_AHI + MROWS*APITCH*2)   // +33792
#define OFF_HS   (OFF_ALO + MROWS*APITCH*2)   // +33792
#define OFF_BIAS (OFF_HS + MROWS*64*4)        // +16384
#define SMEM_DYN (OFF_BIAS + 1536)            // 224768

// ---------------- device-global scratch ----------------
__device__ __align__(16) uint2 g_bs[4 * W_U2];            // per-quarter W fragments (permuted k)
__device__ float    g_h1[BATCH * RDIM];
__device__ uint32_t g_stage[32 * 4 * 2 * (MROWS * 64)];    // [m][q][parity][row*64+hc] = 4MB
__device__ int      g_flag[128];
__device__ float    g_WhhT[RDIM * 768];
__device__ float    g_WlhT[ZCD * RDIM];

// ---------------- helpers ----------------
__device__ __forceinline__ float sigf(float x) { return 1.0f / (1.0f + __expf(-x)); }
__device__ __forceinline__ float tanha(float x) {
    float y; asm("tanh.approx.f32 %0, %1;" : "=f"(y) : "f"(x)); return y;
}
__device__ __forceinline__ uint16_t h_hi(float x) {
    __half h = __float2half_rn(x); return __half_as_ushort(h);
}
__device__ __forceinline__ uint16_t h_lo(float x) {
    __half h = __float2half_rn(x);
    return __half_as_ushort(__float2half_rn(x - __half2float(h)));
}
__device__ __forceinline__ void flag_release(int* p, int v) {
    asm volatile("st.release.gpu.s32 [%0], %1;" :: "l"(p), "r"(v) : "memory");
}
__device__ __forceinline__ int flag_acquire(const int* p) {
    int v; asm volatile("ld.acquire.gpu.s32 %0, [%1];" : "=r"(v) : "l"(p) : "memory");
    return v;
}
__device__ __forceinline__ void mma16816(float* d, uint32_t a0, uint32_t a1, uint32_t a2, uint32_t a3,
                                         uint32_t b0, uint32_t b1) {
    asm volatile(
        "mma.sync.aligned.m16n8k16.row.col.f32.f16.f16.f32 "
        "{%0,%1,%2,%3}, {%4,%5,%6,%7}, {%8,%9}, {%0,%1,%2,%3};"
        : "+f"(d[0]), "+f"(d[1]), "+f"(d[2]), "+f"(d[3])
        : "r"(a0), "r"(a1), "r"(a2), "r"(a3), "r"(b0), "r"(b1));
}

// ---------------- prep: pack fp16 B-fragments (own-quarter-first k order) ----------------
__device__ __forceinline__ float wval_g(const float* Wih, const float* Whh, const float* Wout,
                                        int q, int nt, int qrow, int kp) {
    // permuted k -> real k: quarter rotation, own first
    int k = ((q + (kp >> 6)) & 3) * 64 + (kp & 63);
    if (nt < 32) {
        int col = nt * 8 + qrow;
        int hc  = q * 64 + (col >> 2);
        int g   = col & 3;
        if (g == 0) return Wih[hc*RDIM+k] + Whh[hc*RDIM+k];
        if (g == 1) return Wih[(256+hc)*RDIM+k] + Whh[(256+hc)*RDIM+k];
        if (g == 2) return Wih[(512+hc)*RDIM+k];
        return Whh[(512+hc)*RDIM+k];
    }
    int oc = q * 16 + (nt - 32) * 8 + qrow;
    return Wout[oc*RDIM + k];
}

__global__ void prep_kernel(const float* __restrict__ Wih,
                            const float* __restrict__ Whh,
                            const float* __restrict__ Wout,
                            const float* __restrict__ Wlh) {
    int i0 = blockIdx.x * blockDim.x + threadIdx.x;
    int stride = gridDim.x * blockDim.x;

    const int TOT = 4 * W_U2;
    for (int idx = i0; idx < TOT; idx += stride) {
        int lane = idx & 31;
        int nt   = (idx >> 5) % NTILES;
        int kt   = (idx / (32 * NTILES)) % KTILES;
        int q    = idx / (32 * NTILES * KTILES);
        int qrow = lane >> 2;
        int c    = lane & 3;
        int k0   = kt * 16 + 2 * c;
        float w00 = wval_g(Wih, Whh, Wout, q, nt, qrow, k0);
        float w01 = wval_g(Wih, Whh, Wout, q, nt, qrow, k0 + 1);
        float w10 = wval_g(Wih, Whh, Wout, q, nt, qrow, k0 + 8);
        float w11 = wval_g(Wih, Whh, Wout, q, nt, qrow, k0 + 9);
        uint2 o;
        o.x = (uint32_t)h_hi(w00) | ((uint32_t)h_hi(w01) << 16);
        o.y = (uint32_t)h_hi(w10) | ((uint32_t)h_hi(w11) << 16);
        g_bs[idx] = o;
    }
    for (int idx = i0; idx < RDIM * 768; idx += stride) {
        int k = idx / 768, row = idx % 768;
        g_WhhT[idx] = Whh[row * RDIM + k];
    }
    for (int idx = i0; idx < ZCD * RDIM; idx += stride) {
        int k = idx >> 8, c = idx & 255;
        g_WlhT[idx] = Wlh[c * ZCD + k];
    }
    for (int idx = i0; idx < 128; idx += stride)
        g_flag[idx] = 0;
}

// ---------------- pre-kernel: exact fp32 h0 + step-0 GRU -> g_h1 ----------------
__global__ void __launch_bounds__(256)
pre_kernel(const float* __restrict__ z, const float* __restrict__ xc,
           const float* __restrict__ blh, const float* __restrict__ bih,
           const float* __restrict__ bhh) {
    __shared__ __align__(16) float zc_s[16 * ZCD];
    __shared__ __align__(16) float h0_s[16 * RDIM];
    const int tid  = threadIdx.x;
    const int row0 = blockIdx.x * 16;

    for (int i = tid; i < 16 * HIDD; i += 256) {
        int r = i / HIDD, c = i % HIDD;
        zc_s[r * ZCD + c] = z[(row0 + r) * HIDD + c];
    }
    for (int i = tid; i < 16 * CONDD; i += 256) {
        int r = i / CONDD, c = i % CONDD;
        zc_s[r * ZCD + HIDD + c] = xc[(row0 + r) * CONDD + c];
    }
    __syncthreads();

    {
        float acc[16];
        float bv = blh[tid];
        #pragma unroll
        for (int r = 0; r < 16; ++r) acc[r] = bv;
        for (int k = 0; k < ZCD; ++k) {
            float w = g_WlhT[k * RDIM + tid];
            #pragma unroll
            for (int r = 0; r < 16; ++r)
                acc[r] = fmaf(zc_s[r * ZCD + k], w, acc[r]);
        }
        #pragma unroll
        for (int r = 0; r < 16; ++r) h0_s[r * RDIM + tid] = acc[r];
    }
    __syncthreads();

    float aR[16], aU[16], aH[16];
    #pragma unroll
    for (int r = 0; r < 16; ++r) { aR[r] = 0.f; aU[r] = 0.f; aH[r] = 0.f; }
    for (int k = 0; k < RDIM; ++k) {
        float wr = g_WhhT[k * 768 + tid];
        float wu = g_WhhT[k * 768 + 256 + tid];
        float wn = g_WhhT[k * 768 + 512 + tid];
        #pragma unroll
        for (int r = 0; r < 16; ++r) {
            float hv = h0_s[r * RDIM + k];
            aR[r] = fmaf(hv, wr, aR[r]);
            aU[r] = fmaf(hv, wu, aU[r]);
            aH[r] = fmaf(hv, wn, aH[r]);
        }
    }
    const float br = bih[tid] + bhh[tid];
    const float bu = bih[256 + tid] + bhh[256 + tid];
    const float bi = bih[512 + tid];
    const float bh = bhh[512 + tid];
    #pragma unroll
    for (int r = 0; r < 16; ++r) {
        float rg = sigf(aR[r] + br);
        float ug = sigf(aU[r] + bu);
        float nn = tanhf(fmaf(rg, aH[r] + bh, bi));
        g_h1[(row0 + r) * RDIM + tid] = fmaf(ug, h0_s[r * RDIM + tid] - nn, nn);
    }
}

// ---------------- main persistent 4-way-split kernel (resident weights) ----------------
__global__ void __launch_bounds__(NT, 1)
gru_main_kernel(const float* __restrict__ bih, const float* __restrict__ bhh,
                const float* __restrict__ bout, float* __restrict__ out) {
    extern __shared__ __align__(16) char smem[];
    uint2*    w_s  = reinterpret_cast<uint2*>(smem + OFF_W);
    uint16_t* a_hi = reinterpret_cast<uint16_t*>(smem + OFF_AHI);
    uint16_t* a_lo = reinterpret_cast<uint16_t*>(smem + OFF_ALO);
    float*    h_s  = reinterpret_cast<float*>(smem + OFF_HS);
    float*    bias = reinterpret_cast<float*>(smem + OFF_BIAS);

    const int tid  = threadIdx.x;
    const int wid  = tid >> 5;
    const int lane = tid & 31;
    const int cc   = lane & 3;
    const int gID  = lane >> 2;
    const int m    = blockIdx.x >> 2;
    const int q    = blockIdx.x & 3;
    const int row0 = m * MROWS;
    const int rowA = (wid & 3) * 16 + gID;   // this warp's m16 tile rows
    const int ntbase = (wid >> 2) * 17;      // 17 ntiles per warp

    // ---- resident weights: one-time 136KB L2->SMEM copy ----
    {
        const uint4* wg4 = reinterpret_cast<const uint4*>(g_bs + (size_t)q * W_U2);
        uint4* ws4 = reinterpret_cast<uint4*>(w_s);
        for (int i = tid; i < W_U2 / 2; i += NT) ws4[i] = wg4[i];
    }
    // biases (own 64 hcols + own 16 logit cols)
    if (tid < 64) {
        int H = q * 64 + tid;
        bias[tid]       = bih[H] + bhh[H];
        bias[64 + tid]  = bih[256 + H] + bhh[256 + H];
        bias[128 + tid] = bih[512 + H];
        bias[192 + tid] = bhh[512 + H];
    }
    if (tid < 16) bias[256 + tid] = bout[q * 16 + tid];

    // A planes in PERMUTED column order: kp block d holds quarter (q+d)&3
    for (int i = tid; i < MROWS * RDIM; i += NT) {
        int r = i >> 8, kp = i & 255;
        int k = ((q + (kp >> 6)) & 3) * 64 + (kp & 63);
        float v = g_h1[(row0 + r) * RDIM + k];
        a_hi[r * APITCH + kp] = h_hi(v);
        a_lo[r * APITCH + kp] = h_lo(v);
    }
    for (int i = tid; i < MROWS * 64; i += NT) {
        int r = i >> 6, c = i & 63;
        h_s[i] = g_h1[(row0 + r) * RDIM + q * 64 + c];
    }
    __syncthreads();

    int* my_flag = &g_flag[m * 4 + q];

    #pragma unroll 1
    for (int j = 1; j <= MAXLEN; ++j) {
        float d[17][4];
        #pragma unroll
        for (int n = 0; n < 17; ++n) { d[n][0]=0.f; d[n][1]=0.f; d[n][2]=0.f; d[n][3]=0.f; }

        // ---- K phase 1: ktiles 0-3 (OWN quarter, locally fresh) ----
        #pragma unroll 4
        for (int kt = 0; kt < 4; ++kt) {
            const int k0 = kt * 16 + 2 * cc;
            uint32_t ah0 = *reinterpret_cast<const uint32_t*>(a_hi + rowA * APITCH + k0);
            uint32_t ah1 = *reinterpret_cast<const uint32_t*>(a_hi + (rowA + 8) * APITCH + k0);
            uint32_t ah2 = *reinterpret_cast<const uint32_t*>(a_hi + rowA * APITCH + k0 + 8);
            uint32_t ah3 = *reinterpret_cast<const uint32_t*>(a_hi + (rowA + 8) * APITCH + k0 + 8);
            uint32_t al0 = *reinterpret_cast<const uint32_t*>(a_lo + rowA * APITCH + k0);
            uint32_t al1 = *reinterpret_cast<const uint32_t*>(a_lo + (rowA + 8) * APITCH + k0);
            uint32_t al2 = *reinterpret_cast<const uint32_t*>(a_lo + rowA * APITCH + k0 + 8);
            uint32_t al3 = *reinterpret_cast<const uint32_t*>(a_lo + (rowA + 8) * APITCH + k0 + 8);
            #pragma unroll
            for (int n = 0; n < 17; ++n) {
                uint2 B = w_s[(kt * NTILES + ntbase + n) * 32 + lane];
                mma16816(d[n], ah0, ah1, ah2, ah3, B.x, B.y);
                mma16816(d[n], al0, al1, al2, al3, B.x, B.y);
            }
        }

        // ---- install 3 peers' h_j into A cols [64,256) (one full step of slack) ----
        if (j >= 2) {
            if (tid == 0) {
                #pragma unroll
                for (int dq = 1; dq < 4; ++dq) {
                    const int pq = (q + dq) & 3;
                    while (flag_acquire(&g_flag[m * 4 + pq]) < j - 1) { }
                }
            }
            __syncthreads();
            #pragma unroll
            for (int dq = 1; dq < 4; ++dq) {
                const int pq = (q + dq) & 3;
                const uint4* stg_r = reinterpret_cast<const uint4*>(
                    g_stage + (((size_t)(m * 4 + pq) * 2 + ((j - 1) & 1)) << 12));
                #pragma unroll
                for (int i = 0; i < 4; ++i) {
                    int idx = tid + i * NT;                 // uint4 index (4 u32 = 4 hcols)
                    uint4 v = __ldcg(&stg_r[idx]);
                    int r = idx >> 4, c4 = (idx & 15) * 4;  // 16 uint4 per row
                    uint16_t* ph = a_hi + r * APITCH + dq * 64 + c4;
                    uint16_t* pl = a_lo + r * APITCH + dq * 64 + c4;
                    ph[0] = (uint16_t)(v.x & 0xffffu); pl[0] = (uint16_t)(v.x >> 16);
                    ph[1] = (uint16_t)(v.y & 0xffffu); pl[1] = (uint16_t)(v.y >> 16);
                    ph[2] = (uint16_t)(v.z & 0xffffu); pl[2] = (uint16_t)(v.z >> 16);
                    ph[3] = (uint16_t)(v.w & 0xffffu); pl[3] = (uint16_t)(v.w >> 16);
                }
            }
            __syncthreads();
        }

        // ---- K phase 2: ktiles 4-15 (peer quarters) ----
        #pragma unroll 4
        for (int kt = 4; kt < 16; ++kt) {
            const int k0 = kt * 16 + 2 * cc;
            uint32_t ah0 = *reinterpret_cast<const uint32_t*>(a_hi + rowA * APITCH + k0);
            uint32_t ah1 = *reinterpret_cast<const uint32_t*>(a_hi + (rowA + 8) * APITCH + k0);
            uint32_t ah2 = *reinterpret_cast<const uint32_t*>(a_hi + rowA * APITCH + k0 + 8);
            uint32_t ah3 = *reinterpret_cast<const uint32_t*>(a_hi + (rowA + 8) * APITCH + k0 + 8);
            uint32_t al0 = *reinterpret_cast<const uint32_t*>(a_lo + rowA * APITCH + k0);
            uint32_t al1 = *reinterpret_cast<const uint32_t*>(a_lo + (rowA + 8) * APITCH + k0);
            uint32_t al2 = *reinterpret_cast<const uint32_t*>(a_lo + rowA * APITCH + k0 + 8);
            uint32_t al3 = *reinterpret_cast<const uint32_t*>(a_lo + (rowA + 8) * APITCH + k0 + 8);
            #pragma unroll
            for (int n = 0; n < 17; ++n) {
                uint2 B = w_s[(kt * NTILES + ntbase + n) * 32 + lane];
                mma16816(d[n], ah0, ah1, ah2, ah3, B.x, B.y);
                mma16816(d[n], al0, al1, al2, al3, B.x, B.y);
            }
        }

        // ---- epilogue: gates -> new own h, logits(j-1), staging, flag ----
        uint32_t* stg_w = g_stage + (((size_t)(m * 4 + q) * 2 + (j & 1)) << 12);
        #pragma unroll
        for (int n = 0; n < 17; ++n) {
            const int nt = ntbase + n;
            if (nt < 32) {
                if (j < MAXLEN) {
                    float e0 = __shfl_xor_sync(0xffffffffu, d[n][0], 1);
                    float e1 = __shfl_xor_sync(0xffffffffu, d[n][1], 1);
                    float e2 = __shfl_xor_sync(0xffffffffu, d[n][2], 1);
                    float e3 = __shfl_xor_sync(0xffffffffu, d[n][3], 1);
                    if (!(cc & 1)) {
                        const int hc = nt * 2 + ((lane & 2) >> 1);   // own-local hcol 0..63
                        float rg = sigf(d[n][0] + bias[hc]);
                        float ug = sigf(d[n][1] + bias[64 + hc]);
                        float nn = tanha(fmaf(rg, e1 + bias[192 + hc], e0 + bias[128 + hc]));
                        float ho = h_s[rowA * 64 + hc];
                        float hvA = fmaf(ug, ho - nn, nn);
                        rg = sigf(d[n][2] + bias[hc]);
                        ug = sigf(d[n][3] + bias[64 + hc]);
                        nn = tanha(fmaf(rg, e3 + bias[192 + hc], e2 + bias[128 + hc]));
                        ho = h_s[(rowA + 8) * 64 + hc];
                        float hvB = fmaf(ug, ho - nn, nn);

                        h_s[rowA * 64 + hc]       = hvA;
                        h_s[(rowA + 8) * 64 + hc] = hvB;
                        uint16_t hA = h_hi(hvA), lA = h_lo(hvA);
                        uint16_t hB = h_hi(hvB), lB = h_lo(hvB);
                        a_hi[rowA * APITCH + hc]       = hA;   // own quarter = cols [0,64)
                        a_lo[rowA * APITCH + hc]       = lA;
                        a_hi[(rowA + 8) * APITCH + hc] = hB;
                        a_lo[(rowA + 8) * APITCH + hc] = lB;
                        __stcg(&stg_w[rowA * 64 + hc],       (uint32_t)hA | ((uint32_t)lA << 16));
                        __stcg(&stg_w[(rowA + 8) * 64 + hc], (uint32_t)hB | ((uint32_t)lB << 16));
                    }
                }
            } else {
                const int loc = (nt - 32) * 8 + 2 * cc;      // 0..15
                const int oc  = q * 16 + loc;
                const size_t o0 = ((size_t)(row0 + rowA) * MAXLEN + (j - 1)) * NCHD + oc;
                const size_t o8 = o0 + (size_t)8 * MAXLEN * NCHD;
                out[o0]     = d[n][0] + bias[256 + loc];
                out[o0 + 1] = d[n][1] + bias[256 + loc + 1];
                out[o8]     = d[n][2] + bias[256 + loc];
                out[o8 + 1] = d[n][3] + bias[256 + loc + 1];
            }
        }
        __syncthreads();                 // own A cols + staging complete
        if (j < MAXLEN && tid == 0)
            flag_release(my_flag, j);
    }
}

// ---------------- launcher ----------------
extern "C" void kernel_launch(void* const* d_in, const int* in_sizes, int n_in,
                              void* d_out, int out_size) {
    const float* z     = (const float*)d_in[0];
    const float* xcond = (const float*)d_in[1];
    const float* W_lh  = (const float*)d_in[2];
    const float* b_lh  = (const float*)d_in[3];
    const float* W_ih  = (const float*)d_in[4];
    const float* W_hh  = (const float*)d_in[5];
    const float* b_ih  = (const float*)d_in[6];
    const float* b_hh  = (const float*)d_in[7];
    const float* W_out = (const float*)d_in[8];
    const float* b_out = (const float*)d_in[9];
    float* out = (float*)d_out;

    cudaFuncSetAttribute(gru_main_kernel, cudaFuncAttributeMaxDynamicSharedMemorySize, SMEM_DYN);

    prep_kernel<<<256, 256>>>(W_ih, W_hh, W_out, W_lh);
    pre_kernel<<<128, 256>>>(z, xcond, b_lh, b_ih, b_hh);
    gru_main_kernel<<<NBLK, NT, SMEM_DYN>>>(b_ih, b_hh, b_out, out);
}

// round 11
// speedup vs baseline: 4.8571x; 1.1266x over previous
#include <cuda_runtime.h>
#include <cuda_fp16.h>
#include <cstdint>

// ---------------- problem constants ----------------
#define BATCH   2048
#define RDIM    256
#define HIDD    256
#define CONDD   128
#define ZCD     384
#define NCHD    64
#define MAXLEN  128
#define NBLK    128            // 32 M-tiles x 4 N-quarters
#define NT      512            // 16 warps: (4 m-tiles) x (4 n-groups)
#define MROWS   64             // batch rows per CTA (quartet shares them)
#define NTILES  34             // n8 tiles per CTA: 32 gate (64 hcols x 4) + 2 logit
#define KTILES  16
#define APITCH  264            // u16 pitch of A planes (conflict-free)

#define W_U2    (KTILES*NTILES*32)     // 17408 uint2 = 139264 B
// dynamic smem layout (bytes)
#define OFF_W    0
#define OFF_AHI  139264
#define OFF_ALO  (OFF_AHI + MROWS*APITCH*2)   // +33792
#define OFF_HS   (OFF_ALO + MROWS*APITCH*2)   // +33792
#define OFF_BIAS (OFF_HS + MROWS*64*4)        // +16384
#define SMEM_DYN (OFF_BIAS + 1536)            // 224768

// ---------------- device-global scratch ----------------
__device__ __align__(16) uint2 g_bs[4 * W_U2];            // per-quarter W fragments (permuted k)
__device__ float    g_h1[BATCH * RDIM];
__device__ uint32_t g_stage[32 * 4 * 2 * (MROWS * 64)];    // [m][q][parity][row*64+hc] = 4MB
__device__ int      g_flag[128];
__device__ float    g_WhhT[RDIM * 768];
__device__ float    g_WlhT[ZCD * RDIM];

// ---------------- helpers ----------------
__device__ __forceinline__ float sigf(float x) { return 1.0f / (1.0f + __expf(-x)); }
__device__ __forceinline__ float tanha(float x) {
    float y; asm("tanh.approx.f32 %0, %1;" : "=f"(y) : "f"(x)); return y;
}
__device__ __forceinline__ uint16_t h_hi(float x) {
    __half h = __float2half_rn(x); return __half_as_ushort(h);
}
__device__ __forceinline__ uint16_t h_lo(float x) {
    __half h = __float2half_rn(x);
    return __half_as_ushort(__float2half_rn(x - __half2float(h)));
}
__device__ __forceinline__ void flag_release(int* p, int v) {
    asm volatile("st.release.gpu.s32 [%0], %1;" :: "l"(p), "r"(v) : "memory");
}
__device__ __forceinline__ int flag_acquire(const int* p) {
    int v; asm volatile("ld.acquire.gpu.s32 %0, [%1];" : "=r"(v) : "l"(p) : "memory");
    return v;
}
__device__ __forceinline__ float2 ffma2(float2 a, float2 b, float2 c) {
    unsigned long long au = *reinterpret_cast<unsigned long long*>(&a);
    unsigned long long bu = *reinterpret_cast<unsigned long long*>(&b);
    unsigned long long cu = *reinterpret_cast<unsigned long long*>(&c);
    unsigned long long du;
    asm("fma.rn.f32x2 %0, %1, %2, %3;" : "=l"(du) : "l"(au), "l"(bu), "l"(cu));
    return *reinterpret_cast<float2*>(&du);
}
__device__ __forceinline__ void mma16816(float* d, uint32_t a0, uint32_t a1, uint32_t a2, uint32_t a3,
                                         uint32_t b0, uint32_t b1) {
    asm volatile(
        "mma.sync.aligned.m16n8k16.row.col.f32.f16.f16.f32 "
        "{%0,%1,%2,%3}, {%4,%5,%6,%7}, {%8,%9}, {%0,%1,%2,%3};"
        : "+f"(d[0]), "+f"(d[1]), "+f"(d[2]), "+f"(d[3])
        : "r"(a0), "r"(a1), "r"(a2), "r"(a3), "r"(b0), "r"(b1));
}

// ---------------- prep: pack fp16 B-fragments (own-quarter-first k order) ----------------
__device__ __forceinline__ float wval_g(const float* Wih, const float* Whh, const float* Wout,
                                        int q, int nt, int qrow, int kp) {
    int k = ((q + (kp >> 6)) & 3) * 64 + (kp & 63);
    if (nt < 32) {
        int col = nt * 8 + qrow;
        int hc  = q * 64 + (col >> 2);
        int g   = col & 3;
        if (g == 0) return Wih[hc*RDIM+k] + Whh[hc*RDIM+k];
        if (g == 1) return Wih[(256+hc)*RDIM+k] + Whh[(256+hc)*RDIM+k];
        if (g == 2) return Wih[(512+hc)*RDIM+k];
        return Whh[(512+hc)*RDIM+k];
    }
    int oc = q * 16 + (nt - 32) * 8 + qrow;
    return Wout[oc*RDIM + k];
}

__global__ void prep_kernel(const float* __restrict__ Wih,
                            const float* __restrict__ Whh,
                            const float* __restrict__ Wout,
                            const float* __restrict__ Wlh) {
    int i0 = blockIdx.x * blockDim.x + threadIdx.x;
    int stride = gridDim.x * blockDim.x;

    const int TOT = 4 * W_U2;
    for (int idx = i0; idx < TOT; idx += stride) {
        int lane = idx & 31;
        int nt   = (idx >> 5) % NTILES;
        int kt   = (idx / (32 * NTILES)) % KTILES;
        int q    = idx / (32 * NTILES * KTILES);
        int qrow = lane >> 2;
        int c    = lane & 3;
        int k0   = kt * 16 + 2 * c;
        float w00 = wval_g(Wih, Whh, Wout, q, nt, qrow, k0);
        float w01 = wval_g(Wih, Whh, Wout, q, nt, qrow, k0 + 1);
        float w10 = wval_g(Wih, Whh, Wout, q, nt, qrow, k0 + 8);
        float w11 = wval_g(Wih, Whh, Wout, q, nt, qrow, k0 + 9);
        uint2 o;
        o.x = (uint32_t)h_hi(w00) | ((uint32_t)h_hi(w01) << 16);
        o.y = (uint32_t)h_hi(w10) | ((uint32_t)h_hi(w11) << 16);
        g_bs[idx] = o;
    }
    for (int idx = i0; idx < RDIM * 768; idx += stride) {
        int k = idx / 768, row = idx % 768;
        g_WhhT[idx] = Whh[row * RDIM + k];
    }
    for (int idx = i0; idx < ZCD * RDIM; idx += stride) {
        int k = idx >> 8, c = idx & 255;
        g_WlhT[idx] = Wlh[c * ZCD + k];
    }
    for (int idx = i0; idx < 128; idx += stride)
        g_flag[idx] = 0;
}

// ---------------- pre-kernel (f32x2): exact fp32 h0 + step-0 GRU -> g_h1 ----------------
// Row-paired layout: zc_t[k][r] (pitch 16) and h0_t[c][r] (pitch 18) so that
// float2 loads fetch row pairs and all lanes broadcast the same address.
__global__ void __launch_bounds__(256)
pre_kernel(const float* __restrict__ z, const float* __restrict__ xc,
           const float* __restrict__ blh, const float* __restrict__ bih,
           const float* __restrict__ bhh) {
    __shared__ __align__(16) float zc_t[ZCD * 16];    // 24.6KB, [k*16 + r]
    __shared__ __align__(16) float h0_t[RDIM * 18];   // 18.4KB, [c*18 + r]
    const int tid  = threadIdx.x;
    const int row0 = blockIdx.x * 16;

    // load [z|xc] transposed: addr = k*16 + r, lanes consecutive -> conflict-free
    for (int i = tid; i < 16 * ZCD; i += 256) {
        int r = i & 15, k = i >> 4;
        float v = (k < HIDD) ? z[(row0 + r) * HIDD + k]
                             : xc[(row0 + r) * CONDD + (k - HIDD)];
        zc_t[k * 16 + r] = v;
    }
    __syncthreads();

    // h0: thread = output col (256). 8 row-pair accumulators.
    float2 acc[8];
    {
        float bv = blh[tid];
        #pragma unroll
        for (int rp = 0; rp < 8; ++rp) acc[rp] = make_float2(bv, bv);
        for (int k = 0; k < ZCD; ++k) {
            float w = g_WlhT[k * RDIM + tid];
            float2 w2 = make_float2(w, w);
            #pragma unroll
            for (int rp = 0; rp < 8; ++rp)
                acc[rp] = ffma2(*reinterpret_cast<const float2*>(&zc_t[k * 16 + 2 * rp]), w2, acc[rp]);
        }
        #pragma unroll
        for (int rp = 0; rp < 8; ++rp)
            *reinterpret_cast<float2*>(&h0_t[tid * 18 + 2 * rp]) = acc[rp];
    }
    __syncthreads();

    // step-0 gates: gi = b_ih (x=0), gh = Whh h0 + b_hh
    float2 aR[8], aU[8], aH[8];
    #pragma unroll
    for (int rp = 0; rp < 8; ++rp) {
        aR[rp] = make_float2(0.f, 0.f); aU[rp] = make_float2(0.f, 0.f); aH[rp] = make_float2(0.f, 0.f);
    }
    for (int k = 0; k < RDIM; ++k) {
        float wr = g_WhhT[k * 768 + tid];
        float wu = g_WhhT[k * 768 + 256 + tid];
        float wn = g_WhhT[k * 768 + 512 + tid];
        float2 wr2 = make_float2(wr, wr), wu2 = make_float2(wu, wu), wn2 = make_float2(wn, wn);
        #pragma unroll
        for (int rp = 0; rp < 8; ++rp) {
            float2 h2 = *reinterpret_cast<const float2*>(&h0_t[k * 18 + 2 * rp]);
            aR[rp] = ffma2(h2, wr2, aR[rp]);
            aU[rp] = ffma2(h2, wu2, aU[rp]);
            aH[rp] = ffma2(h2, wn2, aH[rp]);
        }
    }
    const float br = bih[tid] + bhh[tid];
    const float bu = bih[256 + tid] + bhh[256 + tid];
    const float bi = bih[512 + tid];
    const float bh = bhh[512 + tid];
    #pragma unroll
    for (int rp = 0; rp < 8; ++rp) {
        #pragma unroll
        for (int e = 0; e < 2; ++e) {
            int r = 2 * rp + e;
            float gr = e ? aR[rp].y : aR[rp].x;
            float gu = e ? aU[rp].y : aU[rp].x;
            float gh = e ? aH[rp].y : aH[rp].x;
            float rg = sigf(gr + br);
            float ug = sigf(gu + bu);
            float nn = tanhf(fmaf(rg, gh + bh, bi));
            float h0v = h0_t[tid * 18 + r];
            g_h1[(row0 + r) * RDIM + tid] = fmaf(ug, h0v - nn, nn);
        }
    }
}

// ---------------- per-tile device helpers ----------------
__device__ __forceinline__ void gate_tile(const float* d4, int nt, int lane, int cc, int rowA,
                                          float* h_s, uint16_t* a_hi, uint16_t* a_lo,
                                          const float* bias, uint32_t* stg_w) {
    float e0 = __shfl_xor_sync(0xffffffffu, d4[0], 1);
    float e1 = __shfl_xor_sync(0xffffffffu, d4[1], 1);
    float e2 = __shfl_xor_sync(0xffffffffu, d4[2], 1);
    float e3 = __shfl_xor_sync(0xffffffffu, d4[3], 1);
    if (!(cc & 1)) {
        const int hc = nt * 2 + ((lane & 2) >> 1);   // own-local hcol 0..63
        float rg = sigf(d4[0] + bias[hc]);
        float ug = sigf(d4[1] + bias[64 + hc]);
        float nn = tanha(fmaf(rg, e1 + bias[192 + hc], e0 + bias[128 + hc]));
        float ho = h_s[rowA * 64 + hc];
        float hvA = fmaf(ug, ho - nn, nn);
        rg = sigf(d4[2] + bias[hc]);
        ug = sigf(d4[3] + bias[64 + hc]);
        nn = tanha(fmaf(rg, e3 + bias[192 + hc], e2 + bias[128 + hc]));
        ho = h_s[(rowA + 8) * 64 + hc];
        float hvB = fmaf(ug, ho - nn, nn);

        h_s[rowA * 64 + hc]       = hvA;
        h_s[(rowA + 8) * 64 + hc] = hvB;
        uint16_t hA = h_hi(hvA), lA = h_lo(hvA);
        uint16_t hB = h_hi(hvB), lB = h_lo(hvB);
        a_hi[rowA * APITCH + hc]       = hA;   // own quarter = cols [0,64)
        a_lo[rowA * APITCH + hc]       = lA;
        a_hi[(rowA + 8) * APITCH + hc] = hB;
        a_lo[(rowA + 8) * APITCH + hc] = lB;
        __stcg(&stg_w[rowA * 64 + hc],       (uint32_t)hA | ((uint32_t)lA << 16));
        __stcg(&stg_w[(rowA + 8) * 64 + hc], (uint32_t)hB | ((uint32_t)lB << 16));
    }
}

// ---------------- main persistent 4-way-split kernel (resident weights, 16 warps) ----------------
__global__ void __launch_bounds__(NT, 1)
gru_main_kernel(const float* __restrict__ bih, const float* __restrict__ bhh,
                const float* __restrict__ bout, float* __restrict__ out) {
    extern __shared__ __align__(16) char smem[];
    uint2*    w_s  = reinterpret_cast<uint2*>(smem + OFF_W);
    uint16_t* a_hi = reinterpret_cast<uint16_t*>(smem + OFF_AHI);
    uint16_t* a_lo = reinterpret_cast<uint16_t*>(smem + OFF_ALO);
    float*    h_s  = reinterpret_cast<float*>(smem + OFF_HS);
    float*    bias = reinterpret_cast<float*>(smem + OFF_BIAS);

    const int tid  = threadIdx.x;
    const int wid  = tid >> 5;
    const int lane = tid & 31;
    const int cc   = lane & 3;
    const int gID  = lane >> 2;
    const int m    = blockIdx.x >> 2;
    const int q    = blockIdx.x & 3;
    const int row0 = m * MROWS;
    const int mt   = wid & 3;            // m16 tile
    const int g    = wid >> 2;           // n-group
    const int rowA = mt * 16 + gID;
    const int ntbase = (g < 2) ? g * 9 : 18 + (g - 2) * 8;
    const bool has9  = (g < 2);          // groups 0,1 own 9 tiles; 2,3 own 8

    // ---- resident weights: one-time 136KB L2->SMEM copy ----
    {
        const uint4* wg4 = reinterpret_cast<const uint4*>(g_bs + (size_t)q * W_U2);
        uint4* ws4 = reinterpret_cast<uint4*>(w_s);
        for (int i = tid; i < W_U2 / 2; i += NT) ws4[i] = wg4[i];
    }
    if (tid < 64) {
        int H = q * 64 + tid;
        bias[tid]       = bih[H] + bhh[H];
        bias[64 + tid]  = bih[256 + H] + bhh[256 + H];
        bias[128 + tid] = bih[512 + H];
        bias[192 + tid] = bhh[512 + H];
    }
    if (tid < 16) bias[256 + tid] = bout[q * 16 + tid];

    // A planes in PERMUTED column order: kp block d holds quarter (q+d)&3
    for (int i = tid; i < MROWS * RDIM; i += NT) {
        int r = i >> 8, kp = i & 255;
        int k = ((q + (kp >> 6)) & 3) * 64 + (kp & 63);
        float v = g_h1[(row0 + r) * RDIM + k];
        a_hi[r * APITCH + kp] = h_hi(v);
        a_lo[r * APITCH + kp] = h_lo(v);
    }
    for (int i = tid; i < MROWS * 64; i += NT) {
        int r = i >> 6, c = i & 63;
        h_s[i] = g_h1[(row0 + r) * RDIM + q * 64 + c];
    }
    __syncthreads();

    int* my_flag = &g_flag[m * 4 + q];

    #pragma unroll 1
    for (int j = 1; j <= MAXLEN; ++j) {
        float d[9][4];
        #pragma unroll
        for (int n = 0; n < 9; ++n) { d[n][0]=0.f; d[n][1]=0.f; d[n][2]=0.f; d[n][3]=0.f; }

        // ---- K phase 1: ktiles 0-3 (OWN quarter, locally fresh) ----
        #pragma unroll
        for (int kt = 0; kt < 4; ++kt) {
            const int k0 = kt * 16 + 2 * cc;
            uint32_t ah0 = *reinterpret_cast<const uint32_t*>(a_hi + rowA * APITCH + k0);
            uint32_t ah1 = *reinterpret_cast<const uint32_t*>(a_hi + (rowA + 8) * APITCH + k0);
            uint32_t ah2 = *reinterpret_cast<const uint32_t*>(a_hi + rowA * APITCH + k0 + 8);
            uint32_t ah3 = *reinterpret_cast<const uint32_t*>(a_hi + (rowA + 8) * APITCH + k0 + 8);
            uint32_t al0 = *reinterpret_cast<const uint32_t*>(a_lo + rowA * APITCH + k0);
            uint32_t al1 = *reinterpret_cast<const uint32_t*>(a_lo + (rowA + 8) * APITCH + k0);
            uint32_t al2 = *reinterpret_cast<const uint32_t*>(a_lo + rowA * APITCH + k0 + 8);
            uint32_t al3 = *reinterpret_cast<const uint32_t*>(a_lo + (rowA + 8) * APITCH + k0 + 8);
            #pragma unroll
            for (int n = 0; n < 8; ++n) {
                uint2 B = w_s[(kt * NTILES + ntbase + n) * 32 + lane];
                mma16816(d[n], ah0, ah1, ah2, ah3, B.x, B.y);
                mma16816(d[n], al0, al1, al2, al3, B.x, B.y);
            }
            if (has9) {
                uint2 B = w_s[(kt * NTILES + ntbase + 8) * 32 + lane];
                mma16816(d[8], ah0, ah1, ah2, ah3, B.x, B.y);
                mma16816(d[8], al0, al1, al2, al3, B.x, B.y);
            }
        }

        // ---- install 3 peers' h_j into A cols [64,256) (disjoint from phase-1 reads) ----
        if (j >= 2) {
            if (lane == 0) {
                #pragma unroll
                for (int dq = 1; dq < 4; ++dq) {
                    const int pq = (q + dq) & 3;
                    while (flag_acquire(&g_flag[m * 4 + pq]) < j - 1) { }
                }
            }
            __syncwarp();
            #pragma unroll
            for (int dq = 1; dq < 4; ++dq) {
                const int pq = (q + dq) & 3;
                const uint4* stg_r = reinterpret_cast<const uint4*>(
                    g_stage + (((size_t)(m * 4 + pq) * 2 + ((j - 1) & 1)) << 12));
                #pragma unroll
                for (int i = 0; i < 2; ++i) {
                    int idx = tid + i * NT;                 // 1024 uint4 per peer
                    uint4 v = __ldcg(&stg_r[idx]);
                    int r = idx >> 4, c4 = (idx & 15) * 4;  // 16 uint4 per row
                    uint16_t* ph = a_hi + r * APITCH + dq * 64 + c4;
                    uint16_t* pl = a_lo + r * APITCH + dq * 64 + c4;
                    ph[0] = (uint16_t)(v.x & 0xffffu); pl[0] = (uint16_t)(v.x >> 16);
                    ph[1] = (uint16_t)(v.y & 0xffffu); pl[1] = (uint16_t)(v.y >> 16);
                    ph[2] = (uint16_t)(v.z & 0xffffu); pl[2] = (uint16_t)(v.z >> 16);
                    ph[3] = (uint16_t)(v.w & 0xffffu); pl[3] = (uint16_t)(v.w >> 16);
                }
            }
        }
        __syncthreads();   // installs visible to all warps

        // ---- K phase 2: ktiles 4-15 (peer quarters) ----
        #pragma unroll
        for (int kt = 4; kt < 16; ++kt) {
            const int k0 = kt * 16 + 2 * cc;
            uint32_t ah0 = *reinterpret_cast<const uint32_t*>(a_hi + rowA * APITCH + k0);
            uint32_t ah1 = *reinterpret_cast<const uint32_t*>(a_hi + (rowA + 8) * APITCH + k0);
            uint32_t ah2 = *reinterpret_cast<const uint32_t*>(a_hi + rowA * APITCH + k0 + 8);
            uint32_t ah3 = *reinterpret_cast<const uint32_t*>(a_hi + (rowA + 8) * APITCH + k0 + 8);
            uint32_t al0 = *reinterpret_cast<const uint32_t*>(a_lo + rowA * APITCH + k0);
            uint32_t al1 = *reinterpret_cast<const uint32_t*>(a_lo + (rowA + 8) * APITCH + k0);
            uint32_t al2 = *reinterpret_cast<const uint32_t*>(a_lo + rowA * APITCH + k0 + 8);
            uint32_t al3 = *reinterpret_cast<const uint32_t*>(a_lo + (rowA + 8) * APITCH + k0 + 8);
            #pragma unroll
            for (int n = 0; n < 8; ++n) {
                uint2 B = w_s[(kt * NTILES + ntbase + n) * 32 + lane];
                mma16816(d[n], ah0, ah1, ah2, ah3, B.x, B.y);
                mma16816(d[n], al0, al1, al2, al3, B.x, B.y);
            }
            if (has9) {
                uint2 B = w_s[(kt * NTILES + ntbase + 8) * 32 + lane];
                mma16816(d[8], ah0, ah1, ah2, ah3, B.x, B.y);
                mma16816(d[8], al0, al1, al2, al3, B.x, B.y);
            }
        }

        // ---- epilogue: gates -> new own h, logits(j-1), staging, flag ----
        uint32_t* stg_w = g_stage + (((size_t)(m * 4 + q) * 2 + (j & 1)) << 12);
        const int ncnt = has9 ? 9 : 8;
        #pragma unroll
        for (int n = 0; n < 9; ++n) {
            if (n >= ncnt) break;
            const int nt = ntbase + n;
            if (nt < 32) {
                if (j < MAXLEN)
                    gate_tile(d[n], nt, lane, cc, rowA, h_s, a_hi, a_lo, bias, stg_w);
            } else {
                const int loc = (nt - 32) * 8 + 2 * cc;      // 0..15
                const int oc  = q * 16 + loc;
                const size_t o0 = ((size_t)(row0 + rowA) * MAXLEN + (j - 1)) * NCHD + oc;
                const size_t o8 = o0 + (size_t)8 * MAXLEN * NCHD;
                out[o0]     = d[n][0] + bias[256 + loc];
                out[o0 + 1] = d[n][1] + bias[256 + loc + 1];
                out[o8]     = d[n][2] + bias[256 + loc];
                out[o8 + 1] = d[n][3] + bias[256 + loc + 1];
            }
        }
        __syncthreads();                 // own A cols + staging complete
        if (j < MAXLEN && tid == 0)
            flag_release(my_flag, j);
    }
}

// ---------------- launcher ----------------
extern "C" void kernel_launch(void* const* d_in, const int* in_sizes, int n_in,
                              void* d_out, int out_size) {
    const float* z     = (const float*)d_in[0];
    const float* xcond = (const float*)d_in[1];
    const float* W_lh  = (const float*)d_in[2];
    const float* b_lh  = (const float*)d_in[3];
    const float* W_ih  = (const float*)d_in[4];
    const float* W_hh  = (const float*)d_in[5];
    const float* b_ih  = (const float*)d_in[6];
    const float* b_hh  = (const float*)d_in[7];
    const float* W_out = (const float*)d_in[8];
    const float* b_out = (const float*)d_in[9];
    float* out = (float*)d_out;

    cudaFuncSetAttribute(gru_main_kernel, cudaFuncAttributeMaxDynamicSharedMemorySize, SMEM_DYN);

    prep_kernel<<<256, 256>>>(W_ih, W_hh, W_out, W_lh);
    pre_kernel<<<128, 256>>>(z, xcond, b_lh, b_ih, b_hh);
    gru_main_kernel<<<NBLK, NT, SMEM_DYN>>>(b_ih, b_hh, b_out, out);
}